// round 10
// baseline (speedup 1.0000x reference)
#include <cuda_runtime.h>
#include <math.h>
#include <stdint.h>

#define BB 4
#define TT 2048
#define CC 1024
#define NH 16
#define HD 64
#define BT (BB*TT)      // 8192
#define C3 (3*CC)       // 3072

// Scratch (device globals; no allocation allowed)
__device__ float g_qkv[BT * C3];   // [BT, 3C]
__device__ float g_q[BT * CC];     // [B,H,T,64]
__device__ float g_k[BT * CC];
__device__ float g_v[BT * CC];
__device__ float g_attn[BT * CC];  // [B,T,C]  (tf32-rounded by attn epilogue)
__device__ float g_xtf[BT * CC];   // tf32-rounded x
__device__ float g_w1tf[CC * C3];  // tf32-rounded w_qkv
__device__ float g_w2tf[CC * CC];  // tf32-rounded w_out

// ---------------------------------------------------------------------------
// helpers
// ---------------------------------------------------------------------------
__device__ __forceinline__ unsigned f2tf(float x) {
    unsigned r;
    asm("cvt.rna.tf32.f32 %0, %1;" : "=r"(r) : "f"(x));
    return r;
}

// D = A(16x8) * B(8x8) + D  (tf32 in, fp32 accum), row.col
__device__ __forceinline__ void mma8(float* c, const unsigned* a,
                                     unsigned b0, unsigned b1) {
    asm("mma.sync.aligned.m16n8k8.row.col.f32.tf32.tf32.f32 "
        "{%0,%1,%2,%3}, {%4,%5,%6,%7}, {%8,%9}, {%0,%1,%2,%3};"
        : "+f"(c[0]), "+f"(c[1]), "+f"(c[2]), "+f"(c[3])
        : "r"(a[0]), "r"(a[1]), "r"(a[2]), "r"(a[3]), "r"(b0), "r"(b1));
}

__device__ __forceinline__ uint32_t sptr(const void* p) {
    return (uint32_t)__cvta_generic_to_shared(p);
}
__device__ __forceinline__ void cp16(uint32_t dst, const void* src) {
    asm volatile("cp.async.cg.shared.global [%0], [%1], 16;" :: "r"(dst), "l"(src));
}
__device__ __forceinline__ void cp_commit() {
    asm volatile("cp.async.commit_group;");
}
__device__ __forceinline__ void cp_wait0() {
    asm volatile("cp.async.wait_group 0;");
}
__device__ __forceinline__ void cp_wait1() {
    asm volatile("cp.async.wait_group 1;");
}

// ---------------------------------------------------------------------------
// tf32 round pre-pass: out[i] = tf32_rna(in[i]).  n4 = element count / 4.
// ---------------------------------------------------------------------------
__global__ void tf32_round_kernel(const float* __restrict__ in,
                                  float* __restrict__ out, int n4)
{
    int i = blockIdx.x * blockDim.x + threadIdx.x;
    if (i < n4) {
        float4 v = ((const float4*)in)[i];
        uint4 r = make_uint4(f2tf(v.x), f2tf(v.y), f2tf(v.z), f2tf(v.w));
        ((uint4*)out)[i] = r;
    }
}

// ---------------------------------------------------------------------------
// tf32 tensor-core GEMM v3: CTA tile 128x256xK16, 8 warps (2m x 4n),
// warp tile 64x64. Operands MUST already be tf32-rounded (g_xtf etc.) —
// the mainloop has zero cvt / zero STS: cp.async double-buffered straight
// into smem; compute phase is pure fragment-LDS + MMA.
// As: [m][k] stride 20  -> fragment reads conflict-free (20*gid+tig distinct)
// Bs: [k][n] stride 264 -> fragment reads conflict-free (8k+n pattern)
// Requires M%128==0, N%256==0, K%16==0.
// ---------------------------------------------------------------------------
#define GA_STR 20
#define GB_STR 264
#define GA_WORDS (128 * GA_STR)       // 2560
#define GB_WORDS (16 * GB_STR)        // 4224
#define GEMM_SMEM_WORDS (2 * GA_WORDS + 2 * GB_WORDS)

__global__ __launch_bounds__(256) void gemm_tf32(
    const float* __restrict__ A, const float* __restrict__ Bm,
    float* __restrict__ Cm, int M, int N, int K)
{
    extern __shared__ float gsm[];
    float* As[2] = { gsm, gsm + GA_WORDS };
    float* Bs[2] = { gsm + 2 * GA_WORDS, gsm + 2 * GA_WORDS + GB_WORDS };

    int tid = threadIdx.x;
    int lane = tid & 31;
    int warp = tid >> 5;
    int gid = lane >> 2, tig = lane & 3;
    int warp_m = warp >> 2, warp_n = warp & 3;
    int bm = blockIdx.y, bn = blockIdx.x;

    const float* Abase = A + (size_t)(bm * 128) * K;
    const float* Bbase = Bm + (size_t)bn * 256;

    float acc[4][8][4];
    #pragma unroll
    for (int mt = 0; mt < 4; mt++)
        #pragma unroll
        for (int nt = 0; nt < 8; nt++)
            #pragma unroll
            for (int e = 0; e < 4; e++) acc[mt][nt][e] = 0.f;

    // tile issue: A = 128x16 floats (512 16B chunks), B = 16x256 (1024 chunks)
    auto issue = [&](int kt, int buf) {
        #pragma unroll
        for (int it = 0; it < 2; it++) {
            int cid = tid + 256 * it;
            int m = cid >> 2, c = cid & 3;
            cp16(sptr(As[buf] + m * GA_STR + c * 4),
                 Abase + (size_t)m * K + kt * 16 + c * 4);
        }
        #pragma unroll
        for (int it = 0; it < 4; it++) {
            int cid = tid + 256 * it;
            int clo = cid & 7;
            int r = (cid >> 3) & 15;
            int chi = cid >> 7;
            int c = clo + 8 * chi;
            cp16(sptr(Bs[buf] + r * GB_STR + c * 4),
                 Bbase + (size_t)(kt * 16 + r) * N + c * 4);
        }
        cp_commit();
    };

    int ntiles = K / 16;
    issue(0, 0);

    for (int t = 0; t < ntiles; t++) {
        bool has_next = (t + 1 < ntiles);
        if (has_next) issue(t + 1, (t + 1) & 1);
        if (has_next) cp_wait1(); else cp_wait0();
        __syncthreads();

        const float* A_ = As[t & 1];
        const float* B_ = Bs[t & 1];

        #pragma unroll
        for (int ks = 0; ks < 16; ks += 8) {
            unsigned afr[4][4];
            unsigned bfr[8][2];
            #pragma unroll
            for (int mt = 0; mt < 4; mt++) {
                int m = warp_m * 64 + mt * 16 + gid;
                afr[mt][0] = __float_as_uint(A_[m * GA_STR + ks + tig]);
                afr[mt][1] = __float_as_uint(A_[(m + 8) * GA_STR + ks + tig]);
                afr[mt][2] = __float_as_uint(A_[m * GA_STR + ks + tig + 4]);
                afr[mt][3] = __float_as_uint(A_[(m + 8) * GA_STR + ks + tig + 4]);
            }
            #pragma unroll
            for (int nt = 0; nt < 8; nt++) {
                int n = warp_n * 64 + nt * 8 + gid;
                bfr[nt][0] = __float_as_uint(B_[(ks + tig) * GB_STR + n]);
                bfr[nt][1] = __float_as_uint(B_[(ks + tig + 4) * GB_STR + n]);
            }
            #pragma unroll
            for (int mt = 0; mt < 4; mt++)
                #pragma unroll
                for (int nt = 0; nt < 8; nt++)
                    mma8(acc[mt][nt], afr[mt], bfr[nt][0], bfr[nt][1]);
        }
        __syncthreads();   // compute done before buffer t&1 is refilled at t+1
    }

    #pragma unroll
    for (int mt = 0; mt < 4; mt++)
        #pragma unroll
        for (int nt = 0; nt < 8; nt++) {
            int row = bm * 128 + warp_m * 64 + mt * 16 + gid;
            int col = bn * 256 + warp_n * 64 + nt * 8 + tig * 2;
            *(float2*)&Cm[(size_t)row * N + col] =
                make_float2(acc[mt][nt][0], acc[mt][nt][1]);
            *(float2*)&Cm[(size_t)(row + 8) * N + col] =
                make_float2(acc[mt][nt][2], acc[mt][nt][3]);
        }
}

// ---------------------------------------------------------------------------
// Split qkv -> q,k,v in [B,H,T,64] layout; apply RoPE to q,k. (R4 version)
// ---------------------------------------------------------------------------
__global__ void rope_split_kernel()
{
    int idx = blockIdx.x * blockDim.x + threadIdx.x;
    const int total = BB * NH * TT * 32;
    if (idx >= total) return;

    int jj = idx & 31;
    int tmp = idx >> 5;
    int t = tmp & (TT - 1);
    tmp >>= 11;
    int h = tmp & (NH - 1);
    int b = tmp >> 4;

    const float LOG1E4 = 9.210340371976184f;
    float inv_freq = expf(-(float)jj * (LOG1E4 / 32.0f));
    float ang = (float)t * inv_freq;
    float cs = cosf(ang), sn = sinf(ang);

    size_t src_row = (size_t)(b * TT + t) * C3;
    int col = h * HD + jj;

    float q1 = g_qkv[src_row + col];
    float q2 = g_qkv[src_row + col + 32];
    float k1 = g_qkv[src_row + CC + col];
    float k2 = g_qkv[src_row + CC + col + 32];
    float v1 = g_qkv[src_row + 2 * CC + col];
    float v2 = g_qkv[src_row + 2 * CC + col + 32];

    size_t dst = ((size_t)(b * NH + h) * TT + t) * HD + jj;
    g_q[dst]      = q1 * cs - q2 * sn;
    g_q[dst + 32] = q2 * cs + q1 * sn;
    g_k[dst]      = k1 * cs - k2 * sn;
    g_k[dst + 32] = k2 * cs + k1 * sn;
    g_v[dst]      = v1;
    g_v[dst + 32] = v2;
}

// ---------------------------------------------------------------------------
// Flash attention (causal) on tensor cores, tf32 mma — exact R4 kernel;
// only change: epilogue stores tf32-rounded values into g_attn so the
// out-projection GEMM needs no conversion (bit-identical to the old
// f2tf-at-STS in the consumer).
// ---------------------------------------------------------------------------
#define AQ_STR 136
#define AK_STR 72
#define ATTN_SMEM_WORDS (2 * 64 * AQ_STR + 2 * 64 * AK_STR)

__global__ __launch_bounds__(256) void attn_mma_kernel()
{
    extern __shared__ unsigned sm[];
    unsigned* sQ = sm;
    unsigned* sP = sm + 64 * AQ_STR;
    unsigned* sK = sm + 2 * 64 * AQ_STR;
    unsigned* sV = sK + 64 * AK_STR;

    int tid = threadIdx.x;
    int lane = tid & 31;
    int warp = tid >> 5;
    int gid = lane >> 2, tig = lane & 3;
    int qb = blockIdx.x;       // query block 0..15
    int bh = blockIdx.y;       // b*NH + h

    const float* Qg = g_q + ((size_t)bh * TT + qb * 128) * HD;
    const float* Kg = g_k + (size_t)bh * TT * HD;
    const float* Vg = g_v + (size_t)bh * TT * HD;

    // load Q (128x64) -> sQ[d][q], tf32, fold in 1/8 scale
    #pragma unroll
    for (int it = 0; it < 8; it++) {
        int fid = tid + 256 * it;
        int q = fid >> 4;
        int d0 = (fid & 15) * 4;
        float4 v = *(const float4*)(Qg + q * 64 + d0);
        sQ[(d0 + 0) * AQ_STR + q] = f2tf(v.x * 0.125f);
        sQ[(d0 + 1) * AQ_STR + q] = f2tf(v.y * 0.125f);
        sQ[(d0 + 2) * AQ_STR + q] = f2tf(v.z * 0.125f);
        sQ[(d0 + 3) * AQ_STR + q] = f2tf(v.w * 0.125f);
    }

    float oacc[8][4];
    #pragma unroll
    for (int nt = 0; nt < 8; nt++)
        #pragma unroll
        for (int e = 0; e < 4; e++) oacc[nt][e] = 0.f;
    float rm0 = -1e30f, rm1 = -1e30f, rl0 = 0.f, rl1 = 0.f;

    int m_local = warp * 16 + gid;
    int row1 = qb * 128 + m_local;
    int row2 = row1 + 8;

    int kb_max = 2 * qb + 1;
    for (int kb = 0; kb <= kb_max; kb++) {
        __syncthreads();
        #pragma unroll
        for (int it = 0; it < 4; it++) {
            int fid = tid + 256 * it;
            int r = fid >> 4;
            int d0 = (fid & 15) * 4;
            const float* kp = Kg + (size_t)(kb * 64 + r) * 64 + d0;
            float4 kv4 = *(const float4*)kp;
            sK[(d0 + 0) * AK_STR + (r ^ ((((d0 + 0) >> 2) & 7) << 2))] = f2tf(kv4.x);
            sK[(d0 + 1) * AK_STR + (r ^ ((((d0 + 1) >> 2) & 7) << 2))] = f2tf(kv4.y);
            sK[(d0 + 2) * AK_STR + (r ^ ((((d0 + 2) >> 2) & 7) << 2))] = f2tf(kv4.z);
            sK[(d0 + 3) * AK_STR + (r ^ ((((d0 + 3) >> 2) & 7) << 2))] = f2tf(kv4.w);
            const float* vp = Vg + (size_t)(kb * 64 + r) * 64 + d0;
            float4 vv4 = *(const float4*)vp;
            int swzr = ((r >> 2) & 7) << 2;
            uint4 tv = make_uint4(f2tf(vv4.x), f2tf(vv4.y), f2tf(vv4.z), f2tf(vv4.w));
            *(uint4*)&sV[r * AK_STR + (d0 ^ swzr)] = tv;
        }
        __syncthreads();

        float sacc[8][4];
        #pragma unroll
        for (int nt = 0; nt < 8; nt++)
            #pragma unroll
            for (int e = 0; e < 4; e++) sacc[nt][e] = 0.f;

        #pragma unroll
        for (int ks = 0; ks < 64; ks += 8) {
            unsigned a[4];
            a[0] = sQ[(ks + tig) * AQ_STR + m_local];
            a[1] = sQ[(ks + tig) * AQ_STR + m_local + 8];
            a[2] = sQ[(ks + tig + 4) * AQ_STR + m_local];
            a[3] = sQ[(ks + tig + 4) * AQ_STR + m_local + 8];
            int c1 = ((ks >> 2) & 7) << 2;
            int c2 = (((ks + 4) >> 2) & 7) << 2;
            #pragma unroll
            for (int nt = 0; nt < 8; nt++) {
                int n = nt * 8 + gid;
                unsigned b0 = sK[(ks + tig) * AK_STR + (n ^ c1)];
                unsigned b1 = sK[(ks + tig + 4) * AK_STR + (n ^ c2)];
                mma8(sacc[nt], a, b0, b1);
            }
        }

        if (kb >= 2 * qb) {
            #pragma unroll
            for (int nt = 0; nt < 8; nt++) {
                int colb = kb * 64 + nt * 8 + tig * 2;
                if (colb + 0 > row1) sacc[nt][0] = -1e30f;
                if (colb + 1 > row1) sacc[nt][1] = -1e30f;
                if (colb + 0 > row2) sacc[nt][2] = -1e30f;
                if (colb + 1 > row2) sacc[nt][3] = -1e30f;
            }
        }

        float mx0 = -1e30f, mx1 = -1e30f;
        #pragma unroll
        for (int nt = 0; nt < 8; nt++) {
            mx0 = fmaxf(mx0, fmaxf(sacc[nt][0], sacc[nt][1]));
            mx1 = fmaxf(mx1, fmaxf(sacc[nt][2], sacc[nt][3]));
        }
        mx0 = fmaxf(mx0, __shfl_xor_sync(0xffffffffu, mx0, 1));
        mx0 = fmaxf(mx0, __shfl_xor_sync(0xffffffffu, mx0, 2));
        mx1 = fmaxf(mx1, __shfl_xor_sync(0xffffffffu, mx1, 1));
        mx1 = fmaxf(mx1, __shfl_xor_sync(0xffffffffu, mx1, 2));

        float mn0 = fmaxf(rm0, mx0);
        float mn1 = fmaxf(rm1, mx1);
        float corr0 = __expf(rm0 - mn0);
        float corr1 = __expf(rm1 - mn1);
        rm0 = mn0; rm1 = mn1;

        float sum0 = 0.f, sum1 = 0.f;
        #pragma unroll
        for (int nt = 0; nt < 8; nt++) {
            sacc[nt][0] = __expf(sacc[nt][0] - mn0);
            sacc[nt][1] = __expf(sacc[nt][1] - mn0);
            sacc[nt][2] = __expf(sacc[nt][2] - mn1);
            sacc[nt][3] = __expf(sacc[nt][3] - mn1);
            sum0 += sacc[nt][0] + sacc[nt][1];
            sum1 += sacc[nt][2] + sacc[nt][3];
        }
        sum0 += __shfl_xor_sync(0xffffffffu, sum0, 1);
        sum0 += __shfl_xor_sync(0xffffffffu, sum0, 2);
        sum1 += __shfl_xor_sync(0xffffffffu, sum1, 1);
        sum1 += __shfl_xor_sync(0xffffffffu, sum1, 2);
        rl0 = rl0 * corr0 + sum0;
        rl1 = rl1 * corr1 + sum1;

        #pragma unroll
        for (int nt = 0; nt < 8; nt++) {
            oacc[nt][0] *= corr0; oacc[nt][1] *= corr0;
            oacc[nt][2] *= corr1; oacc[nt][3] *= corr1;
        }

        #pragma unroll
        for (int nt = 0; nt < 8; nt++) {
            int kvc = nt * 8 + tig * 2;
            sP[(kvc + 0) * AQ_STR + m_local]     = f2tf(sacc[nt][0]);
            sP[(kvc + 1) * AQ_STR + m_local]     = f2tf(sacc[nt][1]);
            sP[(kvc + 0) * AQ_STR + m_local + 8] = f2tf(sacc[nt][2]);
            sP[(kvc + 1) * AQ_STR + m_local + 8] = f2tf(sacc[nt][3]);
        }
        __syncthreads();

        #pragma unroll
        for (int ks = 0; ks < 64; ks += 8) {
            unsigned a[4];
            a[0] = sP[(ks + tig) * AQ_STR + m_local];
            a[1] = sP[(ks + tig) * AQ_STR + m_local + 8];
            a[2] = sP[(ks + tig + 4) * AQ_STR + m_local];
            a[3] = sP[(ks + tig + 4) * AQ_STR + m_local + 8];
            int c1 = ((ks >> 2) & 7) << 2;
            int c2 = (((ks + 4) >> 2) & 7) << 2;
            #pragma unroll
            for (int nt = 0; nt < 8; nt++) {
                int n = nt * 8 + gid;
                unsigned b0 = sV[(ks + tig) * AK_STR + (n ^ c1)];
                unsigned b1 = sV[(ks + tig + 4) * AK_STR + (n ^ c2)];
                mma8(oacc[nt], a, b0, b1);
            }
        }
    }

    // epilogue: normalize, tf32-round, write to [B,T,C]
    int b = bh >> 4;
    int h = bh & (NH - 1);
    float il0 = 1.f / rl0;
    float il1 = 1.f / rl1;
    #pragma unroll
    for (int nt = 0; nt < 8; nt++) {
        int d = nt * 8 + tig * 2;
        *(float2*)&g_attn[((size_t)(b * TT + row1)) * CC + h * 64 + d] =
            make_float2(__uint_as_float(f2tf(oacc[nt][0] * il0)),
                        __uint_as_float(f2tf(oacc[nt][1] * il0)));
        *(float2*)&g_attn[((size_t)(b * TT + row2)) * CC + h * 64 + d] =
            make_float2(__uint_as_float(f2tf(oacc[nt][2] * il1)),
                        __uint_as_float(f2tf(oacc[nt][3] * il1)));
    }
}

// ---------------------------------------------------------------------------
extern "C" void kernel_launch(void* const* d_in, const int* in_sizes, int n_in,
                              void* d_out, int out_size)
{
    const float* x     = (const float*)d_in[0];
    const float* w_qkv = (const float*)d_in[1];
    const float* w_out = (const float*)d_in[2];
    float* out = (float*)d_out;

    float *qkv_p, *attn_p, *xtf_p, *w1tf_p, *w2tf_p;
    cudaGetSymbolAddress((void**)&qkv_p,  g_qkv);
    cudaGetSymbolAddress((void**)&attn_p, g_attn);
    cudaGetSymbolAddress((void**)&xtf_p,  g_xtf);
    cudaGetSymbolAddress((void**)&w1tf_p, g_w1tf);
    cudaGetSymbolAddress((void**)&w2tf_p, g_w2tf);

    int gemm_smem = GEMM_SMEM_WORDS * sizeof(float);
    cudaFuncSetAttribute(gemm_tf32,
                         cudaFuncAttributeMaxDynamicSharedMemorySize, gemm_smem);

    // 0) tf32-round GEMM operands
    {
        int n4;
        n4 = BT * CC / 4;
        tf32_round_kernel<<<(n4 + 255) / 256, 256>>>(x, xtf_p, n4);
        n4 = CC * C3 / 4;
        tf32_round_kernel<<<(n4 + 255) / 256, 256>>>(w_qkv, w1tf_p, n4);
        n4 = CC * CC / 4;
        tf32_round_kernel<<<(n4 + 255) / 256, 256>>>(w_out, w2tf_p, n4);
    }

    // 1) QKV projection: [8192,1024] @ [1024,3072]   (N tile 256)
    {
        dim3 grid(C3 / 256, BT / 128);
        gemm_tf32<<<grid, 256, gemm_smem>>>(xtf_p, w1tf_p, qkv_p, BT, C3, CC);
    }

    // 2) split + RoPE
    {
        int total = BB * NH * TT * 32;
        rope_split_kernel<<<(total + 255) / 256, 256>>>();
    }

    // 3) flash attention (tensor cores)
    {
        int smem_bytes = ATTN_SMEM_WORDS * sizeof(unsigned);
        cudaFuncSetAttribute(attn_mma_kernel,
                             cudaFuncAttributeMaxDynamicSharedMemorySize,
                             smem_bytes);
        dim3 grid(TT / 128, BB * NH);
        attn_mma_kernel<<<grid, 256, smem_bytes>>>();
    }

    // 4) output projection: [8192,1024] @ [1024,1024]   (N tile 256)
    {
        dim3 grid(CC / 256, BT / 128);
        gemm_tf32<<<grid, 256, gemm_smem>>>(attn_p, w2tf_p, out, BT, CC, CC);
    }
}

// round 12
// speedup vs baseline: 1.7208x; 1.7208x over previous
#include <cuda_runtime.h>
#include <cuda_fp16.h>
#include <math.h>
#include <stdint.h>

#define BB 4
#define TT 2048
#define CC 1024
#define NH 16
#define HD 64
#define BT (BB*TT)      // 8192
#define C3 (3*CC)       // 3072

// Scratch (device globals; no allocation allowed)
__device__ float  g_qkv[BT * C3];    // [BT, 3C] fp32
__device__ __half g_qh[BT * CC];     // [B,H,T,64] fp16, pre-scaled 1/8
__device__ __half g_kh[BT * CC];     // [B,H,T,64] fp16
__device__ __half g_vh[BT * CC];     // [B,H,T,64] fp16
__device__ __half g_attnh[BT * CC];  // [B,T,C] fp16
__device__ __half g_xh[BT * CC];     // fp16 x
__device__ __half g_w1h[C3 * CC];    // w_qkv transposed -> [3C, C] fp16
__device__ __half g_w2h[CC * CC];    // w_out transposed -> [C, C] fp16

// ---------------------------------------------------------------------------
// helpers
// ---------------------------------------------------------------------------
// D(16x8,f32) += A(16x16,f16) * B(16x8,f16)   row.col
__device__ __forceinline__ void mma16(float* c, const unsigned* a,
                                      unsigned b0, unsigned b1) {
    asm("mma.sync.aligned.m16n8k16.row.col.f32.f16.f16.f32 "
        "{%0,%1,%2,%3}, {%4,%5,%6,%7}, {%8,%9}, {%0,%1,%2,%3};"
        : "+f"(c[0]), "+f"(c[1]), "+f"(c[2]), "+f"(c[3])
        : "r"(a[0]), "r"(a[1]), "r"(a[2]), "r"(a[3]), "r"(b0), "r"(b1));
}

__device__ __forceinline__ unsigned h2u(__half2 h) {
    return *reinterpret_cast<unsigned*>(&h);
}

// ---------------------------------------------------------------------------
// fp16 tensor-core GEMM: C[M,N] = A[M,K] @ Bt[N,K]^T, fp32 accum.
// CTA tile 128x128, k-tile 32 halves, 8 warps 2(m) x 4(n), warp 64x32.
// Smem stores half2 pairs along k:  As2[kk][m ^ ((kk>>2)<<2)], stride 136;
// Bs2[kk][n ^ ...], stride 136.  All fragment reads conflict-free.
// Requires M%128==0, N%128==0, K%32==0.
// ---------------------------------------------------------------------------
__global__ __launch_bounds__(256) void gemm_fp16(
    const __half* __restrict__ A, const __half* __restrict__ Bt,
    float* __restrict__ Cm, int M, int N, int K)
{
    __shared__ unsigned As2[16 * 136];
    __shared__ unsigned Bs2[16 * 136];

    int tid = threadIdx.x;
    int lane = tid & 31;
    int warp = tid >> 5;
    int gid = lane >> 2, tig = lane & 3;
    int warp_m = warp >> 2, warp_n = warp & 3;
    int bm = blockIdx.y, bn = blockIdx.x;

    const __half* Ab = A + (size_t)(bm * 128) * K;
    const __half* Bb = Bt + (size_t)(bn * 128) * K;

    float acc[4][4][4];
    #pragma unroll
    for (int mt = 0; mt < 4; mt++)
        #pragma unroll
        for (int nt = 0; nt < 4; nt++)
            #pragma unroll
            for (int e = 0; e < 4; e++) acc[mt][nt][e] = 0.f;

    for (int k0 = 0; k0 < K; k0 += 32) {
        __syncthreads();
        // load A,B tiles: rows x 32 halves; fid -> (row = fid>>2, j = fid&3)
        #pragma unroll
        for (int it = 0; it < 2; it++) {
            int fid = tid + 256 * it;
            int r = fid >> 2;         // 0..127
            int j = fid & 3;          // uint4 index within 32-half row
            uint4 wa = *(const uint4*)(Ab + (size_t)r * K + k0 + 8 * j);
            uint4 wb = *(const uint4*)(Bb + (size_t)r * K + k0 + 8 * j);
            int swz = j << 2;
            As2[(4 * j + 0) * 136 + (r ^ swz)] = wa.x;
            As2[(4 * j + 1) * 136 + (r ^ swz)] = wa.y;
            As2[(4 * j + 2) * 136 + (r ^ swz)] = wa.z;
            As2[(4 * j + 3) * 136 + (r ^ swz)] = wa.w;
            Bs2[(4 * j + 0) * 136 + (r ^ swz)] = wb.x;
            Bs2[(4 * j + 1) * 136 + (r ^ swz)] = wb.y;
            Bs2[(4 * j + 2) * 136 + (r ^ swz)] = wb.z;
            Bs2[(4 * j + 3) * 136 + (r ^ swz)] = wb.w;
        }
        __syncthreads();

        #pragma unroll
        for (int s = 0; s < 2; s++) {
            int c1 = (2 * s) << 2;
            int c2 = (2 * s + 1) << 2;
            unsigned afr[4][4];
            unsigned bfr[4][2];
            #pragma unroll
            for (int mt = 0; mt < 4; mt++) {
                int m = warp_m * 64 + mt * 16 + gid;
                afr[mt][0] = As2[(8 * s + tig) * 136 + (m ^ c1)];
                afr[mt][1] = As2[(8 * s + tig) * 136 + ((m + 8) ^ c1)];
                afr[mt][2] = As2[(8 * s + tig + 4) * 136 + (m ^ c2)];
                afr[mt][3] = As2[(8 * s + tig + 4) * 136 + ((m + 8) ^ c2)];
            }
            #pragma unroll
            for (int nt = 0; nt < 4; nt++) {
                int n = warp_n * 32 + nt * 8 + gid;
                bfr[nt][0] = Bs2[(8 * s + tig) * 136 + (n ^ c1)];
                bfr[nt][1] = Bs2[(8 * s + tig + 4) * 136 + (n ^ c2)];
            }
            #pragma unroll
            for (int mt = 0; mt < 4; mt++)
                #pragma unroll
                for (int nt = 0; nt < 4; nt++)
                    mma16(acc[mt][nt], afr[mt], bfr[nt][0], bfr[nt][1]);
        }
    }

    #pragma unroll
    for (int mt = 0; mt < 4; mt++)
        #pragma unroll
        for (int nt = 0; nt < 4; nt++) {
            int row = bm * 128 + warp_m * 64 + mt * 16 + gid;
            int col = bn * 128 + warp_n * 32 + nt * 8 + tig * 2;
            *(float2*)&Cm[(size_t)row * N + col] =
                make_float2(acc[mt][nt][0], acc[mt][nt][1]);
            *(float2*)&Cm[(size_t)(row + 8) * N + col] =
                make_float2(acc[mt][nt][2], acc[mt][nt][3]);
        }
}

// ---------------------------------------------------------------------------
// pre-passes
// ---------------------------------------------------------------------------
__global__ void fp16_round_kernel(const float* __restrict__ in,
                                  __half* __restrict__ out, int n4)
{
    int i = blockIdx.x * blockDim.x + threadIdx.x;
    if (i < n4) {
        float4 v = ((const float4*)in)[i];
        __half2 h0 = __floats2half2_rn(v.x, v.y);
        __half2 h1 = __floats2half2_rn(v.z, v.w);
        ((__half2*)out)[2 * i]     = h0;
        ((__half2*)out)[2 * i + 1] = h1;
    }
}

__global__ __launch_bounds__(256) void transpose_fp16_kernel(
    const float* __restrict__ in, __half* __restrict__ out, int R, int C)
{   // out[c*R + r] = fp16(in[r*C + c]);  grid (C/32, R/32)
    __shared__ float tile[32][33];
    int r0 = blockIdx.y * 32, c0 = blockIdx.x * 32;
    int tx = threadIdx.x & 31, ty = threadIdx.x >> 5;
    #pragma unroll
    for (int i = ty; i < 32; i += 8)
        tile[i][tx] = in[(size_t)(r0 + i) * C + c0 + tx];
    __syncthreads();
    #pragma unroll
    for (int i = ty; i < 32; i += 8)
        out[(size_t)(c0 + i) * R + r0 + tx] = __float2half_rn(tile[tx][i]);
}

// ---------------------------------------------------------------------------
// Split qkv -> q,k,v in [B,H,T,64] fp16; RoPE on q,k; q pre-scaled by 1/8.
// ---------------------------------------------------------------------------
__global__ void rope_split_kernel()
{
    int idx = blockIdx.x * blockDim.x + threadIdx.x;
    const int total = BB * NH * TT * 32;
    if (idx >= total) return;

    int jj = idx & 31;
    int tmp = idx >> 5;
    int t = tmp & (TT - 1);
    tmp >>= 11;
    int h = tmp & (NH - 1);
    int b = tmp >> 4;

    const float LOG1E4 = 9.210340371976184f;
    float inv_freq = expf(-(float)jj * (LOG1E4 / 32.0f));
    float ang = (float)t * inv_freq;
    float cs = cosf(ang), sn = sinf(ang);

    size_t src_row = (size_t)(b * TT + t) * C3;
    int col = h * HD + jj;

    float q1 = g_qkv[src_row + col];
    float q2 = g_qkv[src_row + col + 32];
    float k1 = g_qkv[src_row + CC + col];
    float k2 = g_qkv[src_row + CC + col + 32];
    float v1 = g_qkv[src_row + 2 * CC + col];
    float v2 = g_qkv[src_row + 2 * CC + col + 32];

    size_t dst = ((size_t)(b * NH + h) * TT + t) * HD + jj;
    g_qh[dst]      = __float2half_rn((q1 * cs - q2 * sn) * 0.125f);
    g_qh[dst + 32] = __float2half_rn((q2 * cs + q1 * sn) * 0.125f);
    g_kh[dst]      = __float2half_rn(k1 * cs - k2 * sn);
    g_kh[dst + 32] = __float2half_rn(k2 * cs + k1 * sn);
    g_vh[dst]      = __float2half_rn(v1);
    g_vh[dst + 32] = __float2half_rn(v2);
}

// ---------------------------------------------------------------------------
// Flash attention (causal), fp16 mma m16n8k16, fp32 accum/softmax.
// CTA = 128 queries, 8 warps; warp w owns rows [16w,16w+16). P stays in
// registers (fp16 C->A relayout is pure packing). Smem ~35KB -> 2 CTAs/SM.
//   sQ2[kk=d/2][q ^ swz]  stride 136
//   sK2[kk=d/2][kv ^ swz] stride 72
//   sV2[kk=kv/2][d ^ swz] stride 72      swz = ((kk>>2)<<2) at store
// ---------------------------------------------------------------------------
__global__ __launch_bounds__(256) void attn_mma_kernel()
{
    __shared__ unsigned sQ2[32 * 136];
    __shared__ unsigned sK2[32 * 72];
    __shared__ unsigned sV2[32 * 72];

    int tid = threadIdx.x;
    int lane = tid & 31;
    int warp = tid >> 5;
    int gid = lane >> 2, tig = lane & 3;
    int qb = blockIdx.x;
    int bh = blockIdx.y;

    const __half* Qg = g_qh + ((size_t)bh * TT + qb * 128) * HD;
    const __half* Kg = g_kh + (size_t)bh * TT * HD;
    const __half* Vg = g_vh + (size_t)bh * TT * HD;

    // load Q (128 q x 64 d): pure uint32 redistribution (already fp16+scaled)
    #pragma unroll
    for (int it = 0; it < 4; it++) {
        int fid = tid + 256 * it;
        int q = fid >> 3;          // 0..127
        int j = fid & 7;           // uint4 within 64-half row
        uint4 w = *(const uint4*)(Qg + (size_t)q * 64 + 8 * j);
        int swz = j << 2;
        sQ2[(4 * j + 0) * 136 + (q ^ swz)] = w.x;
        sQ2[(4 * j + 1) * 136 + (q ^ swz)] = w.y;
        sQ2[(4 * j + 2) * 136 + (q ^ swz)] = w.z;
        sQ2[(4 * j + 3) * 136 + (q ^ swz)] = w.w;
    }

    float oacc[8][4];
    #pragma unroll
    for (int nt = 0; nt < 8; nt++)
        #pragma unroll
        for (int e = 0; e < 4; e++) oacc[nt][e] = 0.f;
    float rm0 = -1e30f, rm1 = -1e30f, rl0 = 0.f, rl1 = 0.f;

    int m_local = warp * 16 + gid;
    int row1 = qb * 128 + m_local;
    int row2 = row1 + 8;

    int kb_max = 2 * qb + 1;
    for (int kb = 0; kb <= kb_max; kb++) {
        __syncthreads();   // prev iter done with sK2/sV2 (and first: Q stores)
        // K tile: 64 kv x 64 d -> sK2[kk_d][kv]
        #pragma unroll
        for (int it = 0; it < 2; it++) {
            int fid = tid + 256 * it;
            int r = fid >> 3;        // kv 0..63
            int j = fid & 7;
            uint4 w = *(const uint4*)(Kg + (size_t)(kb * 64 + r) * 64 + 8 * j);
            int swz = j << 2;
            sK2[(4 * j + 0) * 72 + (r ^ swz)] = w.x;
            sK2[(4 * j + 1) * 72 + (r ^ swz)] = w.y;
            sK2[(4 * j + 2) * 72 + (r ^ swz)] = w.z;
            sK2[(4 * j + 3) * 72 + (r ^ swz)] = w.w;
        }
        // V tile: pairs along kv -> sV2[kk_kv][d]
        {
            int kk = tid >> 3;       // 0..31
            int j = tid & 7;
            const __half2* ra = (const __half2*)(Vg + (size_t)(kb * 64 + 2 * kk) * 64 + 8 * j);
            const __half2* rb = (const __half2*)(Vg + (size_t)(kb * 64 + 2 * kk + 1) * 64 + 8 * j);
            int swz = (kk >> 2) << 2;
            #pragma unroll
            for (int i = 0; i < 4; i++) {
                __half2 a = ra[i], b = rb[i];
                int d = 8 * j + 2 * i;
                sV2[kk * 72 + ((d + 0) ^ swz)] = h2u(__lows2half2(a, b));
                sV2[kk * 72 + ((d + 1) ^ swz)] = h2u(__highs2half2(a, b));
            }
        }
        __syncthreads();

        // S = Q K^T (16 x 64 per warp), 4 k16 steps
        float sacc[8][4];
        #pragma unroll
        for (int nt = 0; nt < 8; nt++)
            #pragma unroll
            for (int e = 0; e < 4; e++) sacc[nt][e] = 0.f;

        #pragma unroll
        for (int s = 0; s < 4; s++) {
            int c1 = (2 * s) << 2;
            int c2 = (2 * s + 1) << 2;
            unsigned a[4];
            a[0] = sQ2[(8 * s + tig) * 136 + (m_local ^ c1)];
            a[1] = sQ2[(8 * s + tig) * 136 + ((m_local + 8) ^ c1)];
            a[2] = sQ2[(8 * s + tig + 4) * 136 + (m_local ^ c2)];
            a[3] = sQ2[(8 * s + tig + 4) * 136 + ((m_local + 8) ^ c2)];
            #pragma unroll
            for (int nt = 0; nt < 8; nt++) {
                int n = nt * 8 + gid;
                unsigned b0 = sK2[(8 * s + tig) * 72 + (n ^ c1)];
                unsigned b1 = sK2[(8 * s + tig + 4) * 72 + (n ^ c2)];
                mma16(sacc[nt], a, b0, b1);
            }
        }

        // causal mask
        if (kb >= 2 * qb) {
            #pragma unroll
            for (int nt = 0; nt < 8; nt++) {
                int colb = kb * 64 + nt * 8 + tig * 2;
                if (colb + 0 > row1) sacc[nt][0] = -1e30f;
                if (colb + 1 > row1) sacc[nt][1] = -1e30f;
                if (colb + 0 > row2) sacc[nt][2] = -1e30f;
                if (colb + 1 > row2) sacc[nt][3] = -1e30f;
            }
        }

        // online softmax (quad reductions), fp32
        float mx0 = -1e30f, mx1 = -1e30f;
        #pragma unroll
        for (int nt = 0; nt < 8; nt++) {
            mx0 = fmaxf(mx0, fmaxf(sacc[nt][0], sacc[nt][1]));
            mx1 = fmaxf(mx1, fmaxf(sacc[nt][2], sacc[nt][3]));
        }
        mx0 = fmaxf(mx0, __shfl_xor_sync(0xffffffffu, mx0, 1));
        mx0 = fmaxf(mx0, __shfl_xor_sync(0xffffffffu, mx0, 2));
        mx1 = fmaxf(mx1, __shfl_xor_sync(0xffffffffu, mx1, 1));
        mx1 = fmaxf(mx1, __shfl_xor_sync(0xffffffffu, mx1, 2));

        float mn0 = fmaxf(rm0, mx0);
        float mn1 = fmaxf(rm1, mx1);
        float corr0 = __expf(rm0 - mn0);
        float corr1 = __expf(rm1 - mn1);
        rm0 = mn0; rm1 = mn1;

        float sum0 = 0.f, sum1 = 0.f;
        #pragma unroll
        for (int nt = 0; nt < 8; nt++) {
            sacc[nt][0] = __expf(sacc[nt][0] - mn0);
            sacc[nt][1] = __expf(sacc[nt][1] - mn0);
            sacc[nt][2] = __expf(sacc[nt][2] - mn1);
            sacc[nt][3] = __expf(sacc[nt][3] - mn1);
            sum0 += sacc[nt][0] + sacc[nt][1];
            sum1 += sacc[nt][2] + sacc[nt][3];
        }
        sum0 += __shfl_xor_sync(0xffffffffu, sum0, 1);
        sum0 += __shfl_xor_sync(0xffffffffu, sum0, 2);
        sum1 += __shfl_xor_sync(0xffffffffu, sum1, 1);
        sum1 += __shfl_xor_sync(0xffffffffu, sum1, 2);
        rl0 = rl0 * corr0 + sum0;
        rl1 = rl1 * corr1 + sum1;

        #pragma unroll
        for (int nt = 0; nt < 8; nt++) {
            oacc[nt][0] *= corr0; oacc[nt][1] *= corr0;
            oacc[nt][2] *= corr1; oacc[nt][3] *= corr1;
        }

        // O += P @ V  — P packed straight from C-fragments (no smem!)
        #pragma unroll
        for (int s = 0; s < 4; s++) {
            unsigned pa[4];
            pa[0] = h2u(__floats2half2_rn(sacc[2 * s][0],     sacc[2 * s][1]));
            pa[1] = h2u(__floats2half2_rn(sacc[2 * s][2],     sacc[2 * s][3]));
            pa[2] = h2u(__floats2half2_rn(sacc[2 * s + 1][0], sacc[2 * s + 1][1]));
            pa[3] = h2u(__floats2half2_rn(sacc[2 * s + 1][2], sacc[2 * s + 1][3]));
            int c1 = (2 * s) << 2;
            int c2 = (2 * s + 1) << 2;
            #pragma unroll
            for (int dt = 0; dt < 8; dt++) {
                int n = dt * 8 + gid;
                unsigned b0 = sV2[(8 * s + tig) * 72 + (n ^ c1)];
                unsigned b1 = sV2[(8 * s + tig + 4) * 72 + (n ^ c2)];
                mma16(oacc[dt], pa, b0, b1);
            }
        }
    }

    // epilogue: normalize, write fp16 [B,T,C]
    int b = bh >> 4;
    int h = bh & (NH - 1);
    float il0 = 1.f / rl0;
    float il1 = 1.f / rl1;
    #pragma unroll
    for (int nt = 0; nt < 8; nt++) {
        int d = nt * 8 + tig * 2;
        *(__half2*)&g_attnh[((size_t)(b * TT + row1)) * CC + h * 64 + d] =
            __floats2half2_rn(oacc[nt][0] * il0, oacc[nt][1] * il0);
        *(__half2*)&g_attnh[((size_t)(b * TT + row2)) * CC + h * 64 + d] =
            __floats2half2_rn(oacc[nt][2] * il1, oacc[nt][3] * il1);
    }
}

// ---------------------------------------------------------------------------
extern "C" void kernel_launch(void* const* d_in, const int* in_sizes, int n_in,
                              void* d_out, int out_size)
{
    const float* x     = (const float*)d_in[0];
    const float* w_qkv = (const float*)d_in[1];
    const float* w_out = (const float*)d_in[2];
    float* out = (float*)d_out;

    float *qkv_p;
    __half *xh_p, *w1h_p, *w2h_p, *attnh_p;
    cudaGetSymbolAddress((void**)&qkv_p,   g_qkv);
    cudaGetSymbolAddress((void**)&xh_p,    g_xh);
    cudaGetSymbolAddress((void**)&w1h_p,   g_w1h);
    cudaGetSymbolAddress((void**)&w2h_p,   g_w2h);
    cudaGetSymbolAddress((void**)&attnh_p, g_attnh);

    // 0) operand prep: fp16 x; transpose+fp16 weights -> [N,K]
    {
        int n4 = BT * CC / 4;
        fp16_round_kernel<<<(n4 + 255) / 256, 256>>>(x, xh_p, n4);
        dim3 g1(C3 / 32, CC / 32);
        transpose_fp16_kernel<<<g1, 256>>>(w_qkv, w1h_p, CC, C3);
        dim3 g2(CC / 32, CC / 32);
        transpose_fp16_kernel<<<g2, 256>>>(w_out, w2h_p, CC, CC);
    }

    // 1) QKV projection: [8192,1024] @ [1024,3072]
    {
        dim3 grid(C3 / 128, BT / 128);
        gemm_fp16<<<grid, 256>>>(xh_p, w1h_p, qkv_p, BT, C3, CC);
    }

    // 2) split + RoPE (fp16 outputs)
    {
        int total = BB * NH * TT * 32;
        rope_split_kernel<<<(total + 255) / 256, 256>>>();
    }

    // 3) flash attention (fp16 tensor cores)
    {
        dim3 grid(TT / 128, BB * NH);
        attn_mma_kernel<<<grid, 256>>>();
    }

    // 4) output projection: [8192,1024] @ [1024,1024]
    {
        dim3 grid(CC / 128, BT / 128);
        gemm_fp16<<<grid, 256>>>(attnh_p, w2h_p, out, BT, CC, CC);
    }
}

// round 13
// speedup vs baseline: 1.8192x; 1.0572x over previous
#include <cuda_runtime.h>
#include <cuda_fp16.h>
#include <math.h>
#include <stdint.h>

#define BB 4
#define TT 2048
#define CC 1024
#define NH 16
#define HD 64
#define BT (BB*TT)      // 8192
#define C3 (3*CC)       // 3072

// Scratch (device globals; no allocation allowed)
__device__ float  g_qkv[BT * C3];    // [BT, 3C] fp32
__device__ __half g_qh[BT * CC];     // [B,H,T,64] fp16, pre-scaled 1/8
__device__ __half g_kh[BT * CC];     // [B,H,T,64] fp16
__device__ __half g_vh[BT * CC];     // [B,H,T,64] fp16
__device__ __half g_attnh[BT * CC];  // [B,T,C] fp16
__device__ __half g_xh[BT * CC];     // fp16 x
__device__ __half g_w1h[C3 * CC];    // w_qkv transposed -> [3C, C] fp16
__device__ __half g_w2h[CC * CC];    // w_out transposed -> [C, C] fp16

// ---------------------------------------------------------------------------
// helpers
// ---------------------------------------------------------------------------
// D(16x8,f32) += A(16x16,f16) * B(16x8,f16)   row.col
__device__ __forceinline__ void mma16(float* c, const unsigned* a,
                                      unsigned b0, unsigned b1) {
    asm("mma.sync.aligned.m16n8k16.row.col.f32.f16.f16.f32 "
        "{%0,%1,%2,%3}, {%4,%5,%6,%7}, {%8,%9}, {%0,%1,%2,%3};"
        : "+f"(c[0]), "+f"(c[1]), "+f"(c[2]), "+f"(c[3])
        : "r"(a[0]), "r"(a[1]), "r"(a[2]), "r"(a[3]), "r"(b0), "r"(b1));
}

__device__ __forceinline__ unsigned h2u(__half2 h) {
    return *reinterpret_cast<unsigned*>(&h);
}

__device__ __forceinline__ void ldsm4(unsigned& r0, unsigned& r1,
                                      unsigned& r2, unsigned& r3,
                                      uint32_t addr) {
    asm volatile("ldmatrix.sync.aligned.m8n8.x4.shared.b16 {%0,%1,%2,%3}, [%4];"
                 : "=r"(r0), "=r"(r1), "=r"(r2), "=r"(r3) : "r"(addr));
}

// ---------------------------------------------------------------------------
// fp16 tensor-core GEMM v2 (ldmatrix): C[M,N] = A[M,K] @ Bt[N,K]^T, fp32 acc.
// CTA tile 128x128, k-tile 32 halves, 8 warps 2(m) x 4(n), warp 64x32.
// Smem: natural k-major rows of 32 halves (64B), 16B-chunk swizzle
// c4 ^= (r>>1)&3  -> STS.128 stores and all ldmatrix phases conflict-free.
// Fragment loads: ldmatrix.x4 (12 per warp-k32 vs 48 scalar LDS before).
// Requires M%128==0, N%128==0, K%32==0.
// ---------------------------------------------------------------------------
__global__ __launch_bounds__(256) void gemm_fp16(
    const __half* __restrict__ A, const __half* __restrict__ Bt,
    float* __restrict__ Cm, int M, int N, int K)
{
    __shared__ __align__(16) __half As[128 * 32];
    __shared__ __align__(16) __half Bs[128 * 32];

    int tid = threadIdx.x;
    int lane = tid & 31;
    int warp = tid >> 5;
    int gid = lane >> 2, tig = lane & 3;
    int warp_m = warp >> 2, warp_n = warp & 3;
    int bm = blockIdx.y, bn = blockIdx.x;

    const __half* Ab = A + (size_t)(bm * 128) * K;
    const __half* Bb = Bt + (size_t)(bn * 128) * K;

    uint32_t asb = (uint32_t)__cvta_generic_to_shared(As);
    uint32_t bsb = (uint32_t)__cvta_generic_to_shared(Bs);

    float acc[4][4][4];
    #pragma unroll
    for (int mt = 0; mt < 4; mt++)
        #pragma unroll
        for (int nt = 0; nt < 4; nt++)
            #pragma unroll
            for (int e = 0; e < 4; e++) acc[mt][nt][e] = 0.f;

    for (int k0 = 0; k0 < K; k0 += 32) {
        __syncthreads();
        #pragma unroll
        for (int it = 0; it < 2; it++) {
            int cid = tid + 256 * it;
            int r = cid >> 2;          // 0..127
            int c4 = cid & 3;          // 16B chunk within 64B row
            int sc = c4 ^ ((r >> 1) & 3);
            uint4 wa = *(const uint4*)(Ab + (size_t)r * K + k0 + 8 * c4);
            uint4 wb = *(const uint4*)(Bb + (size_t)r * K + k0 + 8 * c4);
            *(uint4*)(As + r * 32 + 8 * sc) = wa;
            *(uint4*)(Bs + r * 32 + 8 * sc) = wb;
        }
        __syncthreads();

        #pragma unroll
        for (int s = 0; s < 2; s++) {
            unsigned afr[4][4];
            unsigned bfr[4][2];
            // A fragments: 4 x ldmatrix.x4
            #pragma unroll
            for (int mt = 0; mt < 4; mt++) {
                int m = warp_m * 64 + mt * 16;
                int row = m + (lane & 15);
                int chunk = 2 * s + (lane >> 4);
                int sc = chunk ^ ((row >> 1) & 3);
                ldsm4(afr[mt][0], afr[mt][1], afr[mt][2], afr[mt][3],
                      asb + (row * 32 + 8 * sc) * 2);
            }
            // B fragments: 2 x ldmatrix.x4 (each covers 2 n-tiles)
            #pragma unroll
            for (int nb = 0; nb < 2; nb++) {
                int n0 = warp_n * 32 + nb * 16;
                int row = n0 + (lane & 7) + ((lane >> 4) << 3);
                int chunk = 2 * s + ((lane >> 3) & 1);
                int sc = chunk ^ ((row >> 1) & 3);
                unsigned r0, r1, r2, r3;
                ldsm4(r0, r1, r2, r3, bsb + (row * 32 + 8 * sc) * 2);
                bfr[2 * nb][0] = r0;     bfr[2 * nb][1] = r1;
                bfr[2 * nb + 1][0] = r2; bfr[2 * nb + 1][1] = r3;
            }
            #pragma unroll
            for (int mt = 0; mt < 4; mt++)
                #pragma unroll
                for (int nt = 0; nt < 4; nt++)
                    mma16(acc[mt][nt], afr[mt], bfr[nt][0], bfr[nt][1]);
        }
    }

    #pragma unroll
    for (int mt = 0; mt < 4; mt++)
        #pragma unroll
        for (int nt = 0; nt < 4; nt++) {
            int row = bm * 128 + warp_m * 64 + mt * 16 + gid;
            int col = bn * 128 + warp_n * 32 + nt * 8 + tig * 2;
            *(float2*)&Cm[(size_t)row * N + col] =
                make_float2(acc[mt][nt][0], acc[mt][nt][1]);
            *(float2*)&Cm[(size_t)(row + 8) * N + col] =
                make_float2(acc[mt][nt][2], acc[mt][nt][3]);
        }
}

// ---------------------------------------------------------------------------
// pre-passes
// ---------------------------------------------------------------------------
__global__ void fp16_round_kernel(const float* __restrict__ in,
                                  __half* __restrict__ out, int n4)
{
    int i = blockIdx.x * blockDim.x + threadIdx.x;
    if (i < n4) {
        float4 v = ((const float4*)in)[i];
        __half2 h0 = __floats2half2_rn(v.x, v.y);
        __half2 h1 = __floats2half2_rn(v.z, v.w);
        ((__half2*)out)[2 * i]     = h0;
        ((__half2*)out)[2 * i + 1] = h1;
    }
}

__global__ __launch_bounds__(256) void transpose_fp16_kernel(
    const float* __restrict__ in, __half* __restrict__ out, int R, int C)
{   // out[c*R + r] = fp16(in[r*C + c]);  grid (C/32, R/32)
    __shared__ float tile[32][33];
    int r0 = blockIdx.y * 32, c0 = blockIdx.x * 32;
    int tx = threadIdx.x & 31, ty = threadIdx.x >> 5;
    #pragma unroll
    for (int i = ty; i < 32; i += 8)
        tile[i][tx] = in[(size_t)(r0 + i) * C + c0 + tx];
    __syncthreads();
    #pragma unroll
    for (int i = ty; i < 32; i += 8)
        out[(size_t)(c0 + i) * R + r0 + tx] = __float2half_rn(tile[tx][i]);
}

// ---------------------------------------------------------------------------
// Split qkv -> q,k,v in [B,H,T,64] fp16; RoPE on q,k; q pre-scaled by 1/8.
// ---------------------------------------------------------------------------
__global__ void rope_split_kernel()
{
    int idx = blockIdx.x * blockDim.x + threadIdx.x;
    const int total = BB * NH * TT * 32;
    if (idx >= total) return;

    int jj = idx & 31;
    int tmp = idx >> 5;
    int t = tmp & (TT - 1);
    tmp >>= 11;
    int h = tmp & (NH - 1);
    int b = tmp >> 4;

    const float LOG1E4 = 9.210340371976184f;
    float inv_freq = expf(-(float)jj * (LOG1E4 / 32.0f));
    float ang = (float)t * inv_freq;
    float cs = cosf(ang), sn = sinf(ang);

    size_t src_row = (size_t)(b * TT + t) * C3;
    int col = h * HD + jj;

    float q1 = g_qkv[src_row + col];
    float q2 = g_qkv[src_row + col + 32];
    float k1 = g_qkv[src_row + CC + col];
    float k2 = g_qkv[src_row + CC + col + 32];
    float v1 = g_qkv[src_row + 2 * CC + col];
    float v2 = g_qkv[src_row + 2 * CC + col + 32];

    size_t dst = ((size_t)(b * NH + h) * TT + t) * HD + jj;
    g_qh[dst]      = __float2half_rn((q1 * cs - q2 * sn) * 0.125f);
    g_qh[dst + 32] = __float2half_rn((q2 * cs + q1 * sn) * 0.125f);
    g_kh[dst]      = __float2half_rn(k1 * cs - k2 * sn);
    g_kh[dst + 32] = __float2half_rn(k2 * cs + k1 * sn);
    g_vh[dst]      = __float2half_rn(v1);
    g_vh[dst + 32] = __float2half_rn(v2);
}

// ---------------------------------------------------------------------------
// Flash attention (causal), fp16 mma m16n8k16, fp32 accum/softmax — proven
// R12 kernel, unchanged.
// ---------------------------------------------------------------------------
__global__ __launch_bounds__(256) void attn_mma_kernel()
{
    __shared__ unsigned sQ2[32 * 136];
    __shared__ unsigned sK2[32 * 72];
    __shared__ unsigned sV2[32 * 72];

    int tid = threadIdx.x;
    int lane = tid & 31;
    int warp = tid >> 5;
    int gid = lane >> 2, tig = lane & 3;
    int qb = blockIdx.x;
    int bh = blockIdx.y;

    const __half* Qg = g_qh + ((size_t)bh * TT + qb * 128) * HD;
    const __half* Kg = g_kh + (size_t)bh * TT * HD;
    const __half* Vg = g_vh + (size_t)bh * TT * HD;

    #pragma unroll
    for (int it = 0; it < 4; it++) {
        int fid = tid + 256 * it;
        int q = fid >> 3;
        int j = fid & 7;
        uint4 w = *(const uint4*)(Qg + (size_t)q * 64 + 8 * j);
        int swz = j << 2;
        sQ2[(4 * j + 0) * 136 + (q ^ swz)] = w.x;
        sQ2[(4 * j + 1) * 136 + (q ^ swz)] = w.y;
        sQ2[(4 * j + 2) * 136 + (q ^ swz)] = w.z;
        sQ2[(4 * j + 3) * 136 + (q ^ swz)] = w.w;
    }

    float oacc[8][4];
    #pragma unroll
    for (int nt = 0; nt < 8; nt++)
        #pragma unroll
        for (int e = 0; e < 4; e++) oacc[nt][e] = 0.f;
    float rm0 = -1e30f, rm1 = -1e30f, rl0 = 0.f, rl1 = 0.f;

    int m_local = warp * 16 + gid;
    int row1 = qb * 128 + m_local;
    int row2 = row1 + 8;

    int kb_max = 2 * qb + 1;
    for (int kb = 0; kb <= kb_max; kb++) {
        __syncthreads();
        #pragma unroll
        for (int it = 0; it < 2; it++) {
            int fid = tid + 256 * it;
            int r = fid >> 3;
            int j = fid & 7;
            uint4 w = *(const uint4*)(Kg + (size_t)(kb * 64 + r) * 64 + 8 * j);
            int swz = j << 2;
            sK2[(4 * j + 0) * 72 + (r ^ swz)] = w.x;
            sK2[(4 * j + 1) * 72 + (r ^ swz)] = w.y;
            sK2[(4 * j + 2) * 72 + (r ^ swz)] = w.z;
            sK2[(4 * j + 3) * 72 + (r ^ swz)] = w.w;
        }
        {
            int kk = tid >> 3;
            int j = tid & 7;
            const __half2* ra = (const __half2*)(Vg + (size_t)(kb * 64 + 2 * kk) * 64 + 8 * j);
            const __half2* rb = (const __half2*)(Vg + (size_t)(kb * 64 + 2 * kk + 1) * 64 + 8 * j);
            int swz = (kk >> 2) << 2;
            #pragma unroll
            for (int i = 0; i < 4; i++) {
                __half2 a = ra[i], b = rb[i];
                int d = 8 * j + 2 * i;
                sV2[kk * 72 + ((d + 0) ^ swz)] = h2u(__lows2half2(a, b));
                sV2[kk * 72 + ((d + 1) ^ swz)] = h2u(__highs2half2(a, b));
            }
        }
        __syncthreads();

        float sacc[8][4];
        #pragma unroll
        for (int nt = 0; nt < 8; nt++)
            #pragma unroll
            for (int e = 0; e < 4; e++) sacc[nt][e] = 0.f;

        #pragma unroll
        for (int s = 0; s < 4; s++) {
            int c1 = (2 * s) << 2;
            int c2 = (2 * s + 1) << 2;
            unsigned a[4];
            a[0] = sQ2[(8 * s + tig) * 136 + (m_local ^ c1)];
            a[1] = sQ2[(8 * s + tig) * 136 + ((m_local + 8) ^ c1)];
            a[2] = sQ2[(8 * s + tig + 4) * 136 + (m_local ^ c2)];
            a[3] = sQ2[(8 * s + tig + 4) * 136 + ((m_local + 8) ^ c2)];
            #pragma unroll
            for (int nt = 0; nt < 8; nt++) {
                int n = nt * 8 + gid;
                unsigned b0 = sK2[(8 * s + tig) * 72 + (n ^ c1)];
                unsigned b1 = sK2[(8 * s + tig + 4) * 72 + (n ^ c2)];
                mma16(sacc[nt], a, b0, b1);
            }
        }

        if (kb >= 2 * qb) {
            #pragma unroll
            for (int nt = 0; nt < 8; nt++) {
                int colb = kb * 64 + nt * 8 + tig * 2;
                if (colb + 0 > row1) sacc[nt][0] = -1e30f;
                if (colb + 1 > row1) sacc[nt][1] = -1e30f;
                if (colb + 0 > row2) sacc[nt][2] = -1e30f;
                if (colb + 1 > row2) sacc[nt][3] = -1e30f;
            }
        }

        float mx0 = -1e30f, mx1 = -1e30f;
        #pragma unroll
        for (int nt = 0; nt < 8; nt++) {
            mx0 = fmaxf(mx0, fmaxf(sacc[nt][0], sacc[nt][1]));
            mx1 = fmaxf(mx1, fmaxf(sacc[nt][2], sacc[nt][3]));
        }
        mx0 = fmaxf(mx0, __shfl_xor_sync(0xffffffffu, mx0, 1));
        mx0 = fmaxf(mx0, __shfl_xor_sync(0xffffffffu, mx0, 2));
        mx1 = fmaxf(mx1, __shfl_xor_sync(0xffffffffu, mx1, 1));
        mx1 = fmaxf(mx1, __shfl_xor_sync(0xffffffffu, mx1, 2));

        float mn0 = fmaxf(rm0, mx0);
        float mn1 = fmaxf(rm1, mx1);
        float corr0 = __expf(rm0 - mn0);
        float corr1 = __expf(rm1 - mn1);
        rm0 = mn0; rm1 = mn1;

        float sum0 = 0.f, sum1 = 0.f;
        #pragma unroll
        for (int nt = 0; nt < 8; nt++) {
            sacc[nt][0] = __expf(sacc[nt][0] - mn0);
            sacc[nt][1] = __expf(sacc[nt][1] - mn0);
            sacc[nt][2] = __expf(sacc[nt][2] - mn1);
            sacc[nt][3] = __expf(sacc[nt][3] - mn1);
            sum0 += sacc[nt][0] + sacc[nt][1];
            sum1 += sacc[nt][2] + sacc[nt][3];
        }
        sum0 += __shfl_xor_sync(0xffffffffu, sum0, 1);
        sum0 += __shfl_xor_sync(0xffffffffu, sum0, 2);
        sum1 += __shfl_xor_sync(0xffffffffu, sum1, 1);
        sum1 += __shfl_xor_sync(0xffffffffu, sum1, 2);
        rl0 = rl0 * corr0 + sum0;
        rl1 = rl1 * corr1 + sum1;

        #pragma unroll
        for (int nt = 0; nt < 8; nt++) {
            oacc[nt][0] *= corr0; oacc[nt][1] *= corr0;
            oacc[nt][2] *= corr1; oacc[nt][3] *= corr1;
        }

        #pragma unroll
        for (int s = 0; s < 4; s++) {
            unsigned pa[4];
            pa[0] = h2u(__floats2half2_rn(sacc[2 * s][0],     sacc[2 * s][1]));
            pa[1] = h2u(__floats2half2_rn(sacc[2 * s][2],     sacc[2 * s][3]));
            pa[2] = h2u(__floats2half2_rn(sacc[2 * s + 1][0], sacc[2 * s + 1][1]));
            pa[3] = h2u(__floats2half2_rn(sacc[2 * s + 1][2], sacc[2 * s + 1][3]));
            int c1 = (2 * s) << 2;
            int c2 = (2 * s + 1) << 2;
            #pragma unroll
            for (int dt = 0; dt < 8; dt++) {
                int n = dt * 8 + gid;
                unsigned b0 = sV2[(8 * s + tig) * 72 + (n ^ c1)];
                unsigned b1 = sV2[(8 * s + tig + 4) * 72 + (n ^ c2)];
                mma16(oacc[dt], pa, b0, b1);
            }
        }
    }

    int b = bh >> 4;
    int h = bh & (NH - 1);
    float il0 = 1.f / rl0;
    float il1 = 1.f / rl1;
    #pragma unroll
    for (int nt = 0; nt < 8; nt++) {
        int d = nt * 8 + tig * 2;
        *(__half2*)&g_attnh[((size_t)(b * TT + row1)) * CC + h * 64 + d] =
            __floats2half2_rn(oacc[nt][0] * il0, oacc[nt][1] * il0);
        *(__half2*)&g_attnh[((size_t)(b * TT + row2)) * CC + h * 64 + d] =
            __floats2half2_rn(oacc[nt][2] * il1, oacc[nt][3] * il1);
    }
}

// ---------------------------------------------------------------------------
extern "C" void kernel_launch(void* const* d_in, const int* in_sizes, int n_in,
                              void* d_out, int out_size)
{
    const float* x     = (const float*)d_in[0];
    const float* w_qkv = (const float*)d_in[1];
    const float* w_out = (const float*)d_in[2];
    float* out = (float*)d_out;

    float *qkv_p;
    __half *xh_p, *w1h_p, *w2h_p, *attnh_p;
    cudaGetSymbolAddress((void**)&qkv_p,   g_qkv);
    cudaGetSymbolAddress((void**)&xh_p,    g_xh);
    cudaGetSymbolAddress((void**)&w1h_p,   g_w1h);
    cudaGetSymbolAddress((void**)&w2h_p,   g_w2h);
    cudaGetSymbolAddress((void**)&attnh_p, g_attnh);

    // 0) operand prep: fp16 x; transpose+fp16 weights -> [N,K]
    {
        int n4 = BT * CC / 4;
        fp16_round_kernel<<<(n4 + 255) / 256, 256>>>(x, xh_p, n4);
        dim3 g1(C3 / 32, CC / 32);
        transpose_fp16_kernel<<<g1, 256>>>(w_qkv, w1h_p, CC, C3);
        dim3 g2(CC / 32, CC / 32);
        transpose_fp16_kernel<<<g2, 256>>>(w_out, w2h_p, CC, CC);
    }

    // 1) QKV projection: [8192,1024] @ [1024,3072]
    {
        dim3 grid(C3 / 128, BT / 128);
        gemm_fp16<<<grid, 256>>>(xh_p, w1h_p, qkv_p, BT, C3, CC);
    }

    // 2) split + RoPE (fp16 outputs)
    {
        int total = BB * NH * TT * 32;
        rope_split_kernel<<<(total + 255) / 256, 256>>>();
    }

    // 3) flash attention (fp16 tensor cores)
    {
        dim3 grid(TT / 128, BB * NH);
        attn_mma_kernel<<<grid, 256>>>();
    }

    // 4) output projection: [8192,1024] @ [1024,1024]
    {
        dim3 grid(CC / 128, BT / 128);
        gemm_fp16<<<grid, 256>>>(attnh_p, w2h_p, out, BT, CC, CC);
    }
}

// round 14
// speedup vs baseline: 2.0708x; 1.1383x over previous
#include <cuda_runtime.h>
#include <cuda_fp16.h>
#include <math.h>
#include <stdint.h>

#define BB 4
#define TT 2048
#define CC 1024
#define NH 16
#define HD 64
#define BT (BB*TT)      // 8192
#define C3 (3*CC)       // 3072

// Scratch (device globals; no allocation allowed)
__device__ float  g_qkv[BT * C3];    // [BT, 3C] fp32
__device__ __half g_qh[BT * CC];     // [B,H,T,64] fp16, pre-scaled 1/8
__device__ __half g_kh[BT * CC];     // [B,H,T,64] fp16
__device__ __half g_vh[BT * CC];     // [B,H,T,64] fp16
__device__ __half g_attnh[BT * CC];  // [B,T,C] fp16
__device__ __half g_xh[BT * CC];     // fp16 x
__device__ __half g_w1h[C3 * CC];    // w_qkv transposed -> [3C, C] fp16
__device__ __half g_w2h[CC * CC];    // w_out transposed -> [C, C] fp16

// ---------------------------------------------------------------------------
// helpers
// ---------------------------------------------------------------------------
// D(16x8,f32) += A(16x16,f16) * B(16x8,f16)   row.col
__device__ __forceinline__ void mma16(float* c, const unsigned* a,
                                      unsigned b0, unsigned b1) {
    asm("mma.sync.aligned.m16n8k16.row.col.f32.f16.f16.f32 "
        "{%0,%1,%2,%3}, {%4,%5,%6,%7}, {%8,%9}, {%0,%1,%2,%3};"
        : "+f"(c[0]), "+f"(c[1]), "+f"(c[2]), "+f"(c[3])
        : "r"(a[0]), "r"(a[1]), "r"(a[2]), "r"(a[3]), "r"(b0), "r"(b1));
}

__device__ __forceinline__ unsigned h2u(__half2 h) {
    return *reinterpret_cast<unsigned*>(&h);
}

__device__ __forceinline__ void ldsm4(unsigned& r0, unsigned& r1,
                                      unsigned& r2, unsigned& r3,
                                      uint32_t addr) {
    asm volatile("ldmatrix.sync.aligned.m8n8.x4.shared.b16 {%0,%1,%2,%3}, [%4];"
                 : "=r"(r0), "=r"(r1), "=r"(r2), "=r"(r3) : "r"(addr));
}

__device__ __forceinline__ void cp16(uint32_t dst, const void* src) {
    asm volatile("cp.async.cg.shared.global [%0], [%1], 16;" :: "r"(dst), "l"(src));
}
__device__ __forceinline__ void cp_commit() {
    asm volatile("cp.async.commit_group;");
}
__device__ __forceinline__ void cp_wait0() {
    asm volatile("cp.async.wait_group 0;");
}
__device__ __forceinline__ void cp_wait1() {
    asm volatile("cp.async.wait_group 1;");
}

// ---------------------------------------------------------------------------
// fp16 tensor-core GEMM v3 (ldmatrix + cp.async double buffer):
// C[M,N] = A[M,K] @ Bt[N,K]^T, fp32 accum. CTA tile 128x128, k-tile 32,
// 8 warps 2(m) x 4(n), warp 64x32. Smem per buffer: natural k-major rows of
// 32 halves (64B), 16B-chunk swizzle c4 ^= (r>>1)&3 (stores and all
// ldmatrix phases conflict-free). Tile t+1 cp.async overlaps compute of t.
// Requires M%128==0, N%128==0, K%32==0.
// ---------------------------------------------------------------------------
__global__ __launch_bounds__(256) void gemm_fp16(
    const __half* __restrict__ A, const __half* __restrict__ Bt,
    float* __restrict__ Cm, int M, int N, int K)
{
    __shared__ __align__(16) __half As[2][128 * 32];
    __shared__ __align__(16) __half Bs[2][128 * 32];

    int tid = threadIdx.x;
    int lane = tid & 31;
    int warp = tid >> 5;
    int gid = lane >> 2, tig = lane & 3;
    int warp_m = warp >> 2, warp_n = warp & 3;
    int bm = blockIdx.y, bn = blockIdx.x;

    const __half* Ab = A + (size_t)(bm * 128) * K;
    const __half* Bb = Bt + (size_t)(bn * 128) * K;

    uint32_t asb[2], bsb[2];
    asb[0] = (uint32_t)__cvta_generic_to_shared(As[0]);
    asb[1] = (uint32_t)__cvta_generic_to_shared(As[1]);
    bsb[0] = (uint32_t)__cvta_generic_to_shared(Bs[0]);
    bsb[1] = (uint32_t)__cvta_generic_to_shared(Bs[1]);

    float acc[4][4][4];
    #pragma unroll
    for (int mt = 0; mt < 4; mt++)
        #pragma unroll
        for (int nt = 0; nt < 4; nt++)
            #pragma unroll
            for (int e = 0; e < 4; e++) acc[mt][nt][e] = 0.f;

    // per-thread chunk coords for tile loads (2 chunks each for A and B)
    auto issue = [&](int k0, int buf) {
        #pragma unroll
        for (int it = 0; it < 2; it++) {
            int cid = tid + 256 * it;
            int r = cid >> 2;          // 0..127
            int c4 = cid & 3;          // 16B chunk within 64B row
            int sc = c4 ^ ((r >> 1) & 3);
            cp16(asb[buf] + (r * 32 + 8 * sc) * 2,
                 Ab + (size_t)r * K + k0 + 8 * c4);
            cp16(bsb[buf] + (r * 32 + 8 * sc) * 2,
                 Bb + (size_t)r * K + k0 + 8 * c4);
        }
        cp_commit();
    };

    int T = K / 32;
    issue(0, 0);

    for (int t = 0; t < T; t++) {
        bool has_next = (t + 1 < T);
        if (has_next) issue((t + 1) * 32, (t + 1) & 1);
        if (has_next) cp_wait1(); else cp_wait0();
        __syncthreads();

        int buf = t & 1;
        #pragma unroll
        for (int s = 0; s < 2; s++) {
            unsigned afr[4][4];
            unsigned bfr[4][2];
            // A fragments: 4 x ldmatrix.x4
            #pragma unroll
            for (int mt = 0; mt < 4; mt++) {
                int m = warp_m * 64 + mt * 16;
                int row = m + (lane & 15);
                int chunk = 2 * s + (lane >> 4);
                int sc = chunk ^ ((row >> 1) & 3);
                ldsm4(afr[mt][0], afr[mt][1], afr[mt][2], afr[mt][3],
                      asb[buf] + (row * 32 + 8 * sc) * 2);
            }
            // B fragments: 2 x ldmatrix.x4 (each covers 2 n-tiles)
            #pragma unroll
            for (int nb = 0; nb < 2; nb++) {
                int n0 = warp_n * 32 + nb * 16;
                int row = n0 + (lane & 7) + ((lane >> 4) << 3);
                int chunk = 2 * s + ((lane >> 3) & 1);
                int sc = chunk ^ ((row >> 1) & 3);
                unsigned r0, r1, r2, r3;
                ldsm4(r0, r1, r2, r3, bsb[buf] + (row * 32 + 8 * sc) * 2);
                bfr[2 * nb][0] = r0;     bfr[2 * nb][1] = r1;
                bfr[2 * nb + 1][0] = r2; bfr[2 * nb + 1][1] = r3;
            }
            #pragma unroll
            for (int mt = 0; mt < 4; mt++)
                #pragma unroll
                for (int nt = 0; nt < 4; nt++)
                    mma16(acc[mt][nt], afr[mt], bfr[nt][0], bfr[nt][1]);
        }
        __syncthreads();   // done with buf before it is refilled at t+1's issue
    }

    #pragma unroll
    for (int mt = 0; mt < 4; mt++)
        #pragma unroll
        for (int nt = 0; nt < 4; nt++) {
            int row = bm * 128 + warp_m * 64 + mt * 16 + gid;
            int col = bn * 128 + warp_n * 32 + nt * 8 + tig * 2;
            *(float2*)&Cm[(size_t)row * N + col] =
                make_float2(acc[mt][nt][0], acc[mt][nt][1]);
            *(float2*)&Cm[(size_t)(row + 8) * N + col] =
                make_float2(acc[mt][nt][2], acc[mt][nt][3]);
        }
}

// ---------------------------------------------------------------------------
// pre-passes
// ---------------------------------------------------------------------------
__global__ void fp16_round_kernel(const float* __restrict__ in,
                                  __half* __restrict__ out, int n4)
{
    int i = blockIdx.x * blockDim.x + threadIdx.x;
    if (i < n4) {
        float4 v = ((const float4*)in)[i];
        __half2 h0 = __floats2half2_rn(v.x, v.y);
        __half2 h1 = __floats2half2_rn(v.z, v.w);
        ((__half2*)out)[2 * i]     = h0;
        ((__half2*)out)[2 * i + 1] = h1;
    }
}

__global__ __launch_bounds__(256) void transpose_fp16_kernel(
    const float* __restrict__ in, __half* __restrict__ out, int R, int C)
{   // out[c*R + r] = fp16(in[r*C + c]);  grid (C/32, R/32)
    __shared__ float tile[32][33];
    int r0 = blockIdx.y * 32, c0 = blockIdx.x * 32;
    int tx = threadIdx.x & 31, ty = threadIdx.x >> 5;
    #pragma unroll
    for (int i = ty; i < 32; i += 8)
        tile[i][tx] = in[(size_t)(r0 + i) * C + c0 + tx];
    __syncthreads();
    #pragma unroll
    for (int i = ty; i < 32; i += 8)
        out[(size_t)(c0 + i) * R + r0 + tx] = __float2half_rn(tile[tx][i]);
}

// ---------------------------------------------------------------------------
// Split qkv -> q,k,v in [B,H,T,64] fp16; RoPE on q,k; q pre-scaled by 1/8.
// ---------------------------------------------------------------------------
__global__ void rope_split_kernel()
{
    int idx = blockIdx.x * blockDim.x + threadIdx.x;
    const int total = BB * NH * TT * 32;
    if (idx >= total) return;

    int jj = idx & 31;
    int tmp = idx >> 5;
    int t = tmp & (TT - 1);
    tmp >>= 11;
    int h = tmp & (NH - 1);
    int b = tmp >> 4;

    const float LOG1E4 = 9.210340371976184f;
    float inv_freq = expf(-(float)jj * (LOG1E4 / 32.0f));
    float ang = (float)t * inv_freq;
    float cs = cosf(ang), sn = sinf(ang);

    size_t src_row = (size_t)(b * TT + t) * C3;
    int col = h * HD + jj;

    float q1 = g_qkv[src_row + col];
    float q2 = g_qkv[src_row + col + 32];
    float k1 = g_qkv[src_row + CC + col];
    float k2 = g_qkv[src_row + CC + col + 32];
    float v1 = g_qkv[src_row + 2 * CC + col];
    float v2 = g_qkv[src_row + 2 * CC + col + 32];

    size_t dst = ((size_t)(b * NH + h) * TT + t) * HD + jj;
    g_qh[dst]      = __float2half_rn((q1 * cs - q2 * sn) * 0.125f);
    g_qh[dst + 32] = __float2half_rn((q2 * cs + q1 * sn) * 0.125f);
    g_kh[dst]      = __float2half_rn(k1 * cs - k2 * sn);
    g_kh[dst + 32] = __float2half_rn(k2 * cs + k1 * sn);
    g_vh[dst]      = __float2half_rn(v1);
    g_vh[dst + 32] = __float2half_rn(v2);
}

// ---------------------------------------------------------------------------
// Flash attention (causal), fp16 mma m16n8k16, fp32 accum/softmax — proven
// R12 kernel, unchanged.
// ---------------------------------------------------------------------------
__global__ __launch_bounds__(256) void attn_mma_kernel()
{
    __shared__ unsigned sQ2[32 * 136];
    __shared__ unsigned sK2[32 * 72];
    __shared__ unsigned sV2[32 * 72];

    int tid = threadIdx.x;
    int lane = tid & 31;
    int warp = tid >> 5;
    int gid = lane >> 2, tig = lane & 3;
    int qb = blockIdx.x;
    int bh = blockIdx.y;

    const __half* Qg = g_qh + ((size_t)bh * TT + qb * 128) * HD;
    const __half* Kg = g_kh + (size_t)bh * TT * HD;
    const __half* Vg = g_vh + (size_t)bh * TT * HD;

    #pragma unroll
    for (int it = 0; it < 4; it++) {
        int fid = tid + 256 * it;
        int q = fid >> 3;
        int j = fid & 7;
        uint4 w = *(const uint4*)(Qg + (size_t)q * 64 + 8 * j);
        int swz = j << 2;
        sQ2[(4 * j + 0) * 136 + (q ^ swz)] = w.x;
        sQ2[(4 * j + 1) * 136 + (q ^ swz)] = w.y;
        sQ2[(4 * j + 2) * 136 + (q ^ swz)] = w.z;
        sQ2[(4 * j + 3) * 136 + (q ^ swz)] = w.w;
    }

    float oacc[8][4];
    #pragma unroll
    for (int nt = 0; nt < 8; nt++)
        #pragma unroll
        for (int e = 0; e < 4; e++) oacc[nt][e] = 0.f;
    float rm0 = -1e30f, rm1 = -1e30f, rl0 = 0.f, rl1 = 0.f;

    int m_local = warp * 16 + gid;
    int row1 = qb * 128 + m_local;
    int row2 = row1 + 8;

    int kb_max = 2 * qb + 1;
    for (int kb = 0; kb <= kb_max; kb++) {
        __syncthreads();
        #pragma unroll
        for (int it = 0; it < 2; it++) {
            int fid = tid + 256 * it;
            int r = fid >> 3;
            int j = fid & 7;
            uint4 w = *(const uint4*)(Kg + (size_t)(kb * 64 + r) * 64 + 8 * j);
            int swz = j << 2;
            sK2[(4 * j + 0) * 72 + (r ^ swz)] = w.x;
            sK2[(4 * j + 1) * 72 + (r ^ swz)] = w.y;
            sK2[(4 * j + 2) * 72 + (r ^ swz)] = w.z;
            sK2[(4 * j + 3) * 72 + (r ^ swz)] = w.w;
        }
        {
            int kk = tid >> 3;
            int j = tid & 7;
            const __half2* ra = (const __half2*)(Vg + (size_t)(kb * 64 + 2 * kk) * 64 + 8 * j);
            const __half2* rb = (const __half2*)(Vg + (size_t)(kb * 64 + 2 * kk + 1) * 64 + 8 * j);
            int swz = (kk >> 2) << 2;
            #pragma unroll
            for (int i = 0; i < 4; i++) {
                __half2 a = ra[i], b = rb[i];
                int d = 8 * j + 2 * i;
                sV2[kk * 72 + ((d + 0) ^ swz)] = h2u(__lows2half2(a, b));
                sV2[kk * 72 + ((d + 1) ^ swz)] = h2u(__highs2half2(a, b));
            }
        }
        __syncthreads();

        float sacc[8][4];
        #pragma unroll
        for (int nt = 0; nt < 8; nt++)
            #pragma unroll
            for (int e = 0; e < 4; e++) sacc[nt][e] = 0.f;

        #pragma unroll
        for (int s = 0; s < 4; s++) {
            int c1 = (2 * s) << 2;
            int c2 = (2 * s + 1) << 2;
            unsigned a[4];
            a[0] = sQ2[(8 * s + tig) * 136 + (m_local ^ c1)];
            a[1] = sQ2[(8 * s + tig) * 136 + ((m_local + 8) ^ c1)];
            a[2] = sQ2[(8 * s + tig + 4) * 136 + (m_local ^ c2)];
            a[3] = sQ2[(8 * s + tig + 4) * 136 + ((m_local + 8) ^ c2)];
            #pragma unroll
            for (int nt = 0; nt < 8; nt++) {
                int n = nt * 8 + gid;
                unsigned b0 = sK2[(8 * s + tig) * 72 + (n ^ c1)];
                unsigned b1 = sK2[(8 * s + tig + 4) * 72 + (n ^ c2)];
                mma16(sacc[nt], a, b0, b1);
            }
        }

        if (kb >= 2 * qb) {
            #pragma unroll
            for (int nt = 0; nt < 8; nt++) {
                int colb = kb * 64 + nt * 8 + tig * 2;
                if (colb + 0 > row1) sacc[nt][0] = -1e30f;
                if (colb + 1 > row1) sacc[nt][1] = -1e30f;
                if (colb + 0 > row2) sacc[nt][2] = -1e30f;
                if (colb + 1 > row2) sacc[nt][3] = -1e30f;
            }
        }

        float mx0 = -1e30f, mx1 = -1e30f;
        #pragma unroll
        for (int nt = 0; nt < 8; nt++) {
            mx0 = fmaxf(mx0, fmaxf(sacc[nt][0], sacc[nt][1]));
            mx1 = fmaxf(mx1, fmaxf(sacc[nt][2], sacc[nt][3]));
        }
        mx0 = fmaxf(mx0, __shfl_xor_sync(0xffffffffu, mx0, 1));
        mx0 = fmaxf(mx0, __shfl_xor_sync(0xffffffffu, mx0, 2));
        mx1 = fmaxf(mx1, __shfl_xor_sync(0xffffffffu, mx1, 1));
        mx1 = fmaxf(mx1, __shfl_xor_sync(0xffffffffu, mx1, 2));

        float mn0 = fmaxf(rm0, mx0);
        float mn1 = fmaxf(rm1, mx1);
        float corr0 = __expf(rm0 - mn0);
        float corr1 = __expf(rm1 - mn1);
        rm0 = mn0; rm1 = mn1;

        float sum0 = 0.f, sum1 = 0.f;
        #pragma unroll
        for (int nt = 0; nt < 8; nt++) {
            sacc[nt][0] = __expf(sacc[nt][0] - mn0);
            sacc[nt][1] = __expf(sacc[nt][1] - mn0);
            sacc[nt][2] = __expf(sacc[nt][2] - mn1);
            sacc[nt][3] = __expf(sacc[nt][3] - mn1);
            sum0 += sacc[nt][0] + sacc[nt][1];
            sum1 += sacc[nt][2] + sacc[nt][3];
        }
        sum0 += __shfl_xor_sync(0xffffffffu, sum0, 1);
        sum0 += __shfl_xor_sync(0xffffffffu, sum0, 2);
        sum1 += __shfl_xor_sync(0xffffffffu, sum1, 1);
        sum1 += __shfl_xor_sync(0xffffffffu, sum1, 2);
        rl0 = rl0 * corr0 + sum0;
        rl1 = rl1 * corr1 + sum1;

        #pragma unroll
        for (int nt = 0; nt < 8; nt++) {
            oacc[nt][0] *= corr0; oacc[nt][1] *= corr0;
            oacc[nt][2] *= corr1; oacc[nt][3] *= corr1;
        }

        #pragma unroll
        for (int s = 0; s < 4; s++) {
            unsigned pa[4];
            pa[0] = h2u(__floats2half2_rn(sacc[2 * s][0],     sacc[2 * s][1]));
            pa[1] = h2u(__floats2half2_rn(sacc[2 * s][2],     sacc[2 * s][3]));
            pa[2] = h2u(__floats2half2_rn(sacc[2 * s + 1][0], sacc[2 * s + 1][1]));
            pa[3] = h2u(__floats2half2_rn(sacc[2 * s + 1][2], sacc[2 * s + 1][3]));
            int c1 = (2 * s) << 2;
            int c2 = (2 * s + 1) << 2;
            #pragma unroll
            for (int dt = 0; dt < 8; dt++) {
                int n = dt * 8 + gid;
                unsigned b0 = sV2[(8 * s + tig) * 72 + (n ^ c1)];
                unsigned b1 = sV2[(8 * s + tig + 4) * 72 + (n ^ c2)];
                mma16(oacc[dt], pa, b0, b1);
            }
        }
    }

    int b = bh >> 4;
    int h = bh & (NH - 1);
    float il0 = 1.f / rl0;
    float il1 = 1.f / rl1;
    #pragma unroll
    for (int nt = 0; nt < 8; nt++) {
        int d = nt * 8 + tig * 2;
        *(__half2*)&g_attnh[((size_t)(b * TT + row1)) * CC + h * 64 + d] =
            __floats2half2_rn(oacc[nt][0] * il0, oacc[nt][1] * il0);
        *(__half2*)&g_attnh[((size_t)(b * TT + row2)) * CC + h * 64 + d] =
            __floats2half2_rn(oacc[nt][2] * il1, oacc[nt][3] * il1);
    }
}

// ---------------------------------------------------------------------------
extern "C" void kernel_launch(void* const* d_in, const int* in_sizes, int n_in,
                              void* d_out, int out_size)
{
    const float* x     = (const float*)d_in[0];
    const float* w_qkv = (const float*)d_in[1];
    const float* w_out = (const float*)d_in[2];
    float* out = (float*)d_out;

    float *qkv_p;
    __half *xh_p, *w1h_p, *w2h_p, *attnh_p;
    cudaGetSymbolAddress((void**)&qkv_p,   g_qkv);
    cudaGetSymbolAddress((void**)&xh_p,    g_xh);
    cudaGetSymbolAddress((void**)&w1h_p,   g_w1h);
    cudaGetSymbolAddress((void**)&w2h_p,   g_w2h);
    cudaGetSymbolAddress((void**)&attnh_p, g_attnh);

    // 0) operand prep: fp16 x; transpose+fp16 weights -> [N,K]
    {
        int n4 = BT * CC / 4;
        fp16_round_kernel<<<(n4 + 255) / 256, 256>>>(x, xh_p, n4);
        dim3 g1(C3 / 32, CC / 32);
        transpose_fp16_kernel<<<g1, 256>>>(w_qkv, w1h_p, CC, C3);
        dim3 g2(CC / 32, CC / 32);
        transpose_fp16_kernel<<<g2, 256>>>(w_out, w2h_p, CC, CC);
    }

    // 1) QKV projection: [8192,1024] @ [1024,3072]
    {
        dim3 grid(C3 / 128, BT / 128);
        gemm_fp16<<<grid, 256>>>(xh_p, w1h_p, qkv_p, BT, C3, CC);
    }

    // 2) split + RoPE (fp16 outputs)
    {
        int total = BB * NH * TT * 32;
        rope_split_kernel<<<(total + 255) / 256, 256>>>();
    }

    // 3) flash attention (fp16 tensor cores)
    {
        dim3 grid(TT / 128, BB * NH);
        attn_mma_kernel<<<grid, 256>>>();
    }

    // 4) output projection: [8192,1024] @ [1024,1024]
    {
        dim3 grid(CC / 128, BT / 128);
        gemm_fp16<<<grid, 256>>>(attnh_p, w2h_p, out, BT, CC, CC);
    }
}

// round 15
// speedup vs baseline: 2.1166x; 1.0221x over previous
#include <cuda_runtime.h>
#include <cuda_fp16.h>
#include <math.h>
#include <stdint.h>

#define BB 4
#define TT 2048
#define CC 1024
#define NH 16
#define HD 64
#define BT (BB*TT)      // 8192
#define C3 (3*CC)       // 3072

// Scratch (device globals; no allocation allowed)
__device__ float  g_qkv[BT * C3];    // [BT, 3C] fp32
__device__ __half g_qh[BT * CC];     // [B,H,T,64] fp16, pre-scaled 1/8
__device__ __half g_kh[BT * CC];     // [B,H,T,64] fp16
__device__ __half g_vt[BT * CC];     // [B,H,64,T] fp16  (V transposed!)
__device__ __half g_attnh[BT * CC];  // [B,T,C] fp16
__device__ __half g_xh[BT * CC];     // fp16 x
__device__ __half g_w1h[C3 * CC];    // w_qkv transposed -> [3C, C] fp16
__device__ __half g_w2h[CC * CC];    // w_out transposed -> [C, C] fp16

// ---------------------------------------------------------------------------
// helpers
// ---------------------------------------------------------------------------
// D(16x8,f32) += A(16x16,f16) * B(16x8,f16)   row.col
__device__ __forceinline__ void mma16(float* c, const unsigned* a,
                                      unsigned b0, unsigned b1) {
    asm("mma.sync.aligned.m16n8k16.row.col.f32.f16.f16.f32 "
        "{%0,%1,%2,%3}, {%4,%5,%6,%7}, {%8,%9}, {%0,%1,%2,%3};"
        : "+f"(c[0]), "+f"(c[1]), "+f"(c[2]), "+f"(c[3])
        : "r"(a[0]), "r"(a[1]), "r"(a[2]), "r"(a[3]), "r"(b0), "r"(b1));
}

__device__ __forceinline__ unsigned h2u(__half2 h) {
    return *reinterpret_cast<unsigned*>(&h);
}

__device__ __forceinline__ void ldsm4(unsigned& r0, unsigned& r1,
                                      unsigned& r2, unsigned& r3,
                                      uint32_t addr) {
    asm volatile("ldmatrix.sync.aligned.m8n8.x4.shared.b16 {%0,%1,%2,%3}, [%4];"
                 : "=r"(r0), "=r"(r1), "=r"(r2), "=r"(r3) : "r"(addr));
}

__device__ __forceinline__ void cp16(uint32_t dst, const void* src) {
    asm volatile("cp.async.cg.shared.global [%0], [%1], 16;" :: "r"(dst), "l"(src));
}
__device__ __forceinline__ void cp_commit() {
    asm volatile("cp.async.commit_group;");
}
__device__ __forceinline__ void cp_wait0() {
    asm volatile("cp.async.wait_group 0;");
}
__device__ __forceinline__ void cp_wait1() {
    asm volatile("cp.async.wait_group 1;");
}

// ---------------------------------------------------------------------------
// fp16 tensor-core GEMM (R14, proven): ldmatrix + cp.async double buffer.
// ---------------------------------------------------------------------------
__global__ __launch_bounds__(256) void gemm_fp16(
    const __half* __restrict__ A, const __half* __restrict__ Bt,
    float* __restrict__ Cm, int M, int N, int K)
{
    __shared__ __align__(16) __half As[2][128 * 32];
    __shared__ __align__(16) __half Bs[2][128 * 32];

    int tid = threadIdx.x;
    int lane = tid & 31;
    int warp = tid >> 5;
    int gid = lane >> 2, tig = lane & 3;
    int warp_m = warp >> 2, warp_n = warp & 3;
    int bm = blockIdx.y, bn = blockIdx.x;

    const __half* Ab = A + (size_t)(bm * 128) * K;
    const __half* Bb = Bt + (size_t)(bn * 128) * K;

    uint32_t asb[2], bsb[2];
    asb[0] = (uint32_t)__cvta_generic_to_shared(As[0]);
    asb[1] = (uint32_t)__cvta_generic_to_shared(As[1]);
    bsb[0] = (uint32_t)__cvta_generic_to_shared(Bs[0]);
    bsb[1] = (uint32_t)__cvta_generic_to_shared(Bs[1]);

    float acc[4][4][4];
    #pragma unroll
    for (int mt = 0; mt < 4; mt++)
        #pragma unroll
        for (int nt = 0; nt < 4; nt++)
            #pragma unroll
            for (int e = 0; e < 4; e++) acc[mt][nt][e] = 0.f;

    auto issue = [&](int k0, int buf) {
        #pragma unroll
        for (int it = 0; it < 2; it++) {
            int cid = tid + 256 * it;
            int r = cid >> 2;
            int c4 = cid & 3;
            int sc = c4 ^ ((r >> 1) & 3);
            cp16(asb[buf] + (r * 32 + 8 * sc) * 2,
                 Ab + (size_t)r * K + k0 + 8 * c4);
            cp16(bsb[buf] + (r * 32 + 8 * sc) * 2,
                 Bb + (size_t)r * K + k0 + 8 * c4);
        }
        cp_commit();
    };

    int T = K / 32;
    issue(0, 0);

    for (int t = 0; t < T; t++) {
        bool has_next = (t + 1 < T);
        if (has_next) issue((t + 1) * 32, (t + 1) & 1);
        if (has_next) cp_wait1(); else cp_wait0();
        __syncthreads();

        int buf = t & 1;
        #pragma unroll
        for (int s = 0; s < 2; s++) {
            unsigned afr[4][4];
            unsigned bfr[4][2];
            #pragma unroll
            for (int mt = 0; mt < 4; mt++) {
                int m = warp_m * 64 + mt * 16;
                int row = m + (lane & 15);
                int chunk = 2 * s + (lane >> 4);
                int sc = chunk ^ ((row >> 1) & 3);
                ldsm4(afr[mt][0], afr[mt][1], afr[mt][2], afr[mt][3],
                      asb[buf] + (row * 32 + 8 * sc) * 2);
            }
            #pragma unroll
            for (int nb = 0; nb < 2; nb++) {
                int n0 = warp_n * 32 + nb * 16;
                int row = n0 + (lane & 7) + ((lane >> 4) << 3);
                int chunk = 2 * s + ((lane >> 3) & 1);
                int sc = chunk ^ ((row >> 1) & 3);
                unsigned r0, r1, r2, r3;
                ldsm4(r0, r1, r2, r3, bsb[buf] + (row * 32 + 8 * sc) * 2);
                bfr[2 * nb][0] = r0;     bfr[2 * nb][1] = r1;
                bfr[2 * nb + 1][0] = r2; bfr[2 * nb + 1][1] = r3;
            }
            #pragma unroll
            for (int mt = 0; mt < 4; mt++)
                #pragma unroll
                for (int nt = 0; nt < 4; nt++)
                    mma16(acc[mt][nt], afr[mt], bfr[nt][0], bfr[nt][1]);
        }
        __syncthreads();
    }

    #pragma unroll
    for (int mt = 0; mt < 4; mt++)
        #pragma unroll
        for (int nt = 0; nt < 4; nt++) {
            int row = bm * 128 + warp_m * 64 + mt * 16 + gid;
            int col = bn * 128 + warp_n * 32 + nt * 8 + tig * 2;
            *(float2*)&Cm[(size_t)row * N + col] =
                make_float2(acc[mt][nt][0], acc[mt][nt][1]);
            *(float2*)&Cm[(size_t)(row + 8) * N + col] =
                make_float2(acc[mt][nt][2], acc[mt][nt][3]);
        }
}

// ---------------------------------------------------------------------------
// pre-passes
// ---------------------------------------------------------------------------
__global__ void fp16_round_kernel(const float* __restrict__ in,
                                  __half* __restrict__ out, int n4)
{
    int i = blockIdx.x * blockDim.x + threadIdx.x;
    if (i < n4) {
        float4 v = ((const float4*)in)[i];
        __half2 h0 = __floats2half2_rn(v.x, v.y);
        __half2 h1 = __floats2half2_rn(v.z, v.w);
        ((__half2*)out)[2 * i]     = h0;
        ((__half2*)out)[2 * i + 1] = h1;
    }
}

__global__ __launch_bounds__(256) void transpose_fp16_kernel(
    const float* __restrict__ in, __half* __restrict__ out, int R, int C)
{   // out[c*R + r] = fp16(in[r*C + c]);  grid (C/32, R/32)
    __shared__ float tile[32][33];
    int r0 = blockIdx.y * 32, c0 = blockIdx.x * 32;
    int tx = threadIdx.x & 31, ty = threadIdx.x >> 5;
    #pragma unroll
    for (int i = ty; i < 32; i += 8)
        tile[i][tx] = in[(size_t)(r0 + i) * C + c0 + tx];
    __syncthreads();
    #pragma unroll
    for (int i = ty; i < 32; i += 8)
        out[(size_t)(c0 + i) * R + r0 + tx] = __float2half_rn(tile[tx][i]);
}

// ---------------------------------------------------------------------------
// Split qkv -> q,k [B,H,T,64], V TRANSPOSED [B,H,64,T]; RoPE; q scaled 1/8.
// ---------------------------------------------------------------------------
__global__ void rope_split_kernel()
{
    int idx = blockIdx.x * blockDim.x + threadIdx.x;
    const int total = BB * NH * TT * 32;
    if (idx >= total) return;

    int jj = idx & 31;
    int tmp = idx >> 5;
    int t = tmp & (TT - 1);
    tmp >>= 11;
    int h = tmp & (NH - 1);
    int b = tmp >> 4;
    int bh = b * NH + h;

    const float LOG1E4 = 9.210340371976184f;
    float inv_freq = expf(-(float)jj * (LOG1E4 / 32.0f));
    float ang = (float)t * inv_freq;
    float cs = cosf(ang), sn = sinf(ang);

    size_t src_row = (size_t)(b * TT + t) * C3;
    int col = h * HD + jj;

    float q1 = g_qkv[src_row + col];
    float q2 = g_qkv[src_row + col + 32];
    float k1 = g_qkv[src_row + CC + col];
    float k2 = g_qkv[src_row + CC + col + 32];
    float v1 = g_qkv[src_row + 2 * CC + col];
    float v2 = g_qkv[src_row + 2 * CC + col + 32];

    size_t dst = ((size_t)bh * TT + t) * HD + jj;
    g_qh[dst]      = __float2half_rn((q1 * cs - q2 * sn) * 0.125f);
    g_qh[dst + 32] = __float2half_rn((q2 * cs + q1 * sn) * 0.125f);
    g_kh[dst]      = __float2half_rn(k1 * cs - k2 * sn);
    g_kh[dst + 32] = __float2half_rn(k2 * cs + k1 * sn);

    // V transposed: [bh][d][t]
    size_t vdst = ((size_t)bh * HD + jj) * TT + t;
    g_vt[vdst]           = __float2half_rn(v1);
    g_vt[vdst + 32 * TT] = __float2half_rn(v2);
}

// ---------------------------------------------------------------------------
// Flash attention (causal), fp16 mma, v3: cp.async double-buffered K/V,
// row-major [row][kk] smem layouts (stride 36 words, conflict-free fragment
// reads via the stride stagger, verbatim 16B copies from gmem). V comes from
// the transposed g_vt so its pair-packing is free. Q fragments hoisted to
// registers at kb==0. Values bit-identical to R14.
// Smem (uint32): sQ[128*36] | sK[2][64*36] | sV[2][64*36]  = 54 KB dynamic.
// ---------------------------------------------------------------------------
#define AT_QW (128 * 36)
#define AT_KW (64 * 36)
#define ATTN_SMEM_WORDS (AT_QW + 4 * AT_KW)

__global__ __launch_bounds__(256) void attn_mma_kernel()
{
    extern __shared__ unsigned smw[];
    unsigned* sQ = smw;
    unsigned* sK[2] = { smw + AT_QW, smw + AT_QW + AT_KW };
    unsigned* sV[2] = { smw + AT_QW + 2 * AT_KW, smw + AT_QW + 3 * AT_KW };

    int tid = threadIdx.x;
    int lane = tid & 31;
    int warp = tid >> 5;
    int gid = lane >> 2, tig = lane & 3;
    int qb = blockIdx.x;
    int bh = blockIdx.y;

    const __half* Qg = g_qh + ((size_t)bh * TT + qb * 128) * HD;
    const __half* Kg = g_kh + (size_t)bh * TT * HD;
    const __half* VTg = g_vt + (size_t)bh * HD * TT;   // [d][t]

    uint32_t qsb = (uint32_t)__cvta_generic_to_shared(sQ);
    uint32_t ksb[2], vsb[2];
    ksb[0] = (uint32_t)__cvta_generic_to_shared(sK[0]);
    ksb[1] = (uint32_t)__cvta_generic_to_shared(sK[1]);
    vsb[0] = (uint32_t)__cvta_generic_to_shared(sV[0]);
    vsb[1] = (uint32_t)__cvta_generic_to_shared(sV[1]);

    auto issue_kv = [&](int kb, int buf) {
        #pragma unroll
        for (int i = 0; i < 2; i++) {
            int cid = tid + 256 * i;
            int r = cid >> 3;          // 0..63
            int j = cid & 7;           // 16B chunk (8 halves)
            cp16(ksb[buf] + (r * 36 + 4 * j) * 4,
                 Kg + (size_t)(kb * 64 + r) * 64 + 8 * j);
            cp16(vsb[buf] + (r * 36 + 4 * j) * 4,
                 VTg + (size_t)r * TT + kb * 64 + 8 * j);
        }
        cp_commit();
    };

    // Q chunks (group shared with tile 0)
    #pragma unroll
    for (int i = 0; i < 4; i++) {
        int cid = tid + 256 * i;
        int r = cid >> 3;              // 0..127
        int j = cid & 7;
        cp16(qsb + (r * 36 + 4 * j) * 4, Qg + (size_t)r * 64 + 8 * j);
    }
    issue_kv(0, 0);   // commits Q + K/V tile 0

    float oacc[8][4];
    #pragma unroll
    for (int nt = 0; nt < 8; nt++)
        #pragma unroll
        for (int e = 0; e < 4; e++) oacc[nt][e] = 0.f;
    float rm0 = -1e30f, rm1 = -1e30f, rl0 = 0.f, rl1 = 0.f;

    int m_local = warp * 16 + gid;
    int row1 = qb * 128 + m_local;
    int row2 = row1 + 8;

    unsigned qa[4][4];   // Q fragments, filled at kb==0

    int kb_max = 2 * qb + 1;
    for (int kb = 0; kb <= kb_max; kb++) {
        bool has_next = (kb < kb_max);
        if (has_next) issue_kv(kb + 1, (kb + 1) & 1);
        if (has_next) cp_wait1(); else cp_wait0();
        __syncthreads();

        int buf = kb & 1;
        const unsigned* K_ = sK[buf];
        const unsigned* V_ = sV[buf];

        if (kb == 0) {
            #pragma unroll
            for (int s = 0; s < 4; s++) {
                qa[s][0] = sQ[m_local * 36 + 8 * s + tig];
                qa[s][1] = sQ[(m_local + 8) * 36 + 8 * s + tig];
                qa[s][2] = sQ[m_local * 36 + 8 * s + tig + 4];
                qa[s][3] = sQ[(m_local + 8) * 36 + 8 * s + tig + 4];
            }
        }

        // S = Q K^T (16 x 64 per warp), 4 k16 steps
        float sacc[8][4];
        #pragma unroll
        for (int nt = 0; nt < 8; nt++)
            #pragma unroll
            for (int e = 0; e < 4; e++) sacc[nt][e] = 0.f;

        #pragma unroll
        for (int s = 0; s < 4; s++) {
            #pragma unroll
            for (int nt = 0; nt < 8; nt++) {
                int n = nt * 8 + gid;
                unsigned b0 = K_[n * 36 + 8 * s + tig];
                unsigned b1 = K_[n * 36 + 8 * s + tig + 4];
                mma16(sacc[nt], qa[s], b0, b1);
            }
        }

        // causal mask
        if (kb >= 2 * qb) {
            #pragma unroll
            for (int nt = 0; nt < 8; nt++) {
                int colb = kb * 64 + nt * 8 + tig * 2;
                if (colb + 0 > row1) sacc[nt][0] = -1e30f;
                if (colb + 1 > row1) sacc[nt][1] = -1e30f;
                if (colb + 0 > row2) sacc[nt][2] = -1e30f;
                if (colb + 1 > row2) sacc[nt][3] = -1e30f;
            }
        }

        // online softmax (quad reductions), fp32
        float mx0 = -1e30f, mx1 = -1e30f;
        #pragma unroll
        for (int nt = 0; nt < 8; nt++) {
            mx0 = fmaxf(mx0, fmaxf(sacc[nt][0], sacc[nt][1]));
            mx1 = fmaxf(mx1, fmaxf(sacc[nt][2], sacc[nt][3]));
        }
        mx0 = fmaxf(mx0, __shfl_xor_sync(0xffffffffu, mx0, 1));
        mx0 = fmaxf(mx0, __shfl_xor_sync(0xffffffffu, mx0, 2));
        mx1 = fmaxf(mx1, __shfl_xor_sync(0xffffffffu, mx1, 1));
        mx1 = fmaxf(mx1, __shfl_xor_sync(0xffffffffu, mx1, 2));

        float mn0 = fmaxf(rm0, mx0);
        float mn1 = fmaxf(rm1, mx1);
        float corr0 = __expf(rm0 - mn0);
        float corr1 = __expf(rm1 - mn1);
        rm0 = mn0; rm1 = mn1;

        float sum0 = 0.f, sum1 = 0.f;
        #pragma unroll
        for (int nt = 0; nt < 8; nt++) {
            sacc[nt][0] = __expf(sacc[nt][0] - mn0);
            sacc[nt][1] = __expf(sacc[nt][1] - mn0);
            sacc[nt][2] = __expf(sacc[nt][2] - mn1);
            sacc[nt][3] = __expf(sacc[nt][3] - mn1);
            sum0 += sacc[nt][0] + sacc[nt][1];
            sum1 += sacc[nt][2] + sacc[nt][3];
        }
        sum0 += __shfl_xor_sync(0xffffffffu, sum0, 1);
        sum0 += __shfl_xor_sync(0xffffffffu, sum0, 2);
        sum1 += __shfl_xor_sync(0xffffffffu, sum1, 1);
        sum1 += __shfl_xor_sync(0xffffffffu, sum1, 2);
        rl0 = rl0 * corr0 + sum0;
        rl1 = rl1 * corr1 + sum1;

        #pragma unroll
        for (int nt = 0; nt < 8; nt++) {
            oacc[nt][0] *= corr0; oacc[nt][1] *= corr0;
            oacc[nt][2] *= corr1; oacc[nt][3] *= corr1;
        }

        // O += P @ V  — P packed straight from C-fragments
        #pragma unroll
        for (int s = 0; s < 4; s++) {
            unsigned pa[4];
            pa[0] = h2u(__floats2half2_rn(sacc[2 * s][0],     sacc[2 * s][1]));
            pa[1] = h2u(__floats2half2_rn(sacc[2 * s][2],     sacc[2 * s][3]));
            pa[2] = h2u(__floats2half2_rn(sacc[2 * s + 1][0], sacc[2 * s + 1][1]));
            pa[3] = h2u(__floats2half2_rn(sacc[2 * s + 1][2], sacc[2 * s + 1][3]));
            #pragma unroll
            for (int dt = 0; dt < 8; dt++) {
                int n = dt * 8 + gid;
                unsigned b0 = V_[n * 36 + 8 * s + tig];
                unsigned b1 = V_[n * 36 + 8 * s + tig + 4];
                mma16(oacc[dt], pa, b0, b1);
            }
        }
        __syncthreads();   // done with buf before refill next iteration
    }

    // epilogue: normalize, write fp16 [B,T,C]
    int b = bh >> 4;
    int h = bh & (NH - 1);
    float il0 = 1.f / rl0;
    float il1 = 1.f / rl1;
    #pragma unroll
    for (int nt = 0; nt < 8; nt++) {
        int d = nt * 8 + tig * 2;
        *(__half2*)&g_attnh[((size_t)(b * TT + row1)) * CC + h * 64 + d] =
            __floats2half2_rn(oacc[nt][0] * il0, oacc[nt][1] * il0);
        *(__half2*)&g_attnh[((size_t)(b * TT + row2)) * CC + h * 64 + d] =
            __floats2half2_rn(oacc[nt][2] * il1, oacc[nt][3] * il1);
    }
}

// ---------------------------------------------------------------------------
extern "C" void kernel_launch(void* const* d_in, const int* in_sizes, int n_in,
                              void* d_out, int out_size)
{
    const float* x     = (const float*)d_in[0];
    const float* w_qkv = (const float*)d_in[1];
    const float* w_out = (const float*)d_in[2];
    float* out = (float*)d_out;

    float *qkv_p;
    __half *xh_p, *w1h_p, *w2h_p, *attnh_p;
    cudaGetSymbolAddress((void**)&qkv_p,   g_qkv);
    cudaGetSymbolAddress((void**)&xh_p,    g_xh);
    cudaGetSymbolAddress((void**)&w1h_p,   g_w1h);
    cudaGetSymbolAddress((void**)&w2h_p,   g_w2h);
    cudaGetSymbolAddress((void**)&attnh_p, g_attnh);

    // 0) operand prep: fp16 x; transpose+fp16 weights -> [N,K]
    {
        int n4 = BT * CC / 4;
        fp16_round_kernel<<<(n4 + 255) / 256, 256>>>(x, xh_p, n4);
        dim3 g1(C3 / 32, CC / 32);
        transpose_fp16_kernel<<<g1, 256>>>(w_qkv, w1h_p, CC, C3);
        dim3 g2(CC / 32, CC / 32);
        transpose_fp16_kernel<<<g2, 256>>>(w_out, w2h_p, CC, CC);
    }

    // 1) QKV projection: [8192,1024] @ [1024,3072]
    {
        dim3 grid(C3 / 128, BT / 128);
        gemm_fp16<<<grid, 256>>>(xh_p, w1h_p, qkv_p, BT, C3, CC);
    }

    // 2) split + RoPE (fp16 outputs; V transposed)
    {
        int total = BB * NH * TT * 32;
        rope_split_kernel<<<(total + 255) / 256, 256>>>();
    }

    // 3) flash attention (fp16 tensor cores, cp.async double-buffered)
    {
        int smem_bytes = ATTN_SMEM_WORDS * sizeof(unsigned);
        cudaFuncSetAttribute(attn_mma_kernel,
                             cudaFuncAttributeMaxDynamicSharedMemorySize,
                             smem_bytes);
        dim3 grid(TT / 128, BB * NH);
        attn_mma_kernel<<<grid, 256, smem_bytes>>>();
    }

    // 4) output projection: [8192,1024] @ [1024,1024]
    {
        dim3 grid(CC / 128, BT / 128);
        gemm_fp16<<<grid, 256>>>(attnh_p, w2h_p, out, BT, CC, CC);
    }
}

// round 16
// speedup vs baseline: 2.2297x; 1.0534x over previous
#include <cuda_runtime.h>
#include <cuda_fp16.h>
#include <math.h>
#include <stdint.h>

#define BB 4
#define TT 2048
#define CC 1024
#define NH 16
#define HD 64
#define BT (BB*TT)      // 8192
#define C3 (3*CC)       // 3072

// Scratch (device globals; no allocation allowed)
__device__ float  g_qkv[BT * C3];    // [BT, 3C] fp32
__device__ __half g_qh[BT * CC];     // [B,H,T,64] fp16, pre-scaled 1/8
__device__ __half g_kh[BT * CC];     // [B,H,T,64] fp16
__device__ __half g_vt[BT * CC];     // [B,H,64,T] fp16  (V transposed)
__device__ __half g_attnh[BT * CC];  // [B,T,C] fp16
__device__ __half g_xh[BT * CC];     // fp16 x
__device__ __half g_w1h[C3 * CC];    // w_qkv transposed -> [3C, C] fp16
__device__ __half g_w2h[CC * CC];    // w_out transposed -> [C, C] fp16

// ---------------------------------------------------------------------------
// helpers
// ---------------------------------------------------------------------------
__device__ __forceinline__ void mma16(float* c, const unsigned* a,
                                      unsigned b0, unsigned b1) {
    asm("mma.sync.aligned.m16n8k16.row.col.f32.f16.f16.f32 "
        "{%0,%1,%2,%3}, {%4,%5,%6,%7}, {%8,%9}, {%0,%1,%2,%3};"
        : "+f"(c[0]), "+f"(c[1]), "+f"(c[2]), "+f"(c[3])
        : "r"(a[0]), "r"(a[1]), "r"(a[2]), "r"(a[3]), "r"(b0), "r"(b1));
}

__device__ __forceinline__ unsigned h2u(__half2 h) {
    return *reinterpret_cast<unsigned*>(&h);
}

__device__ __forceinline__ void ldsm4(unsigned& r0, unsigned& r1,
                                      unsigned& r2, unsigned& r3,
                                      uint32_t addr) {
    asm volatile("ldmatrix.sync.aligned.m8n8.x4.shared.b16 {%0,%1,%2,%3}, [%4];"
                 : "=r"(r0), "=r"(r1), "=r"(r2), "=r"(r3) : "r"(addr));
}

__device__ __forceinline__ void cp16(uint32_t dst, const void* src) {
    asm volatile("cp.async.cg.shared.global [%0], [%1], 16;" :: "r"(dst), "l"(src));
}
__device__ __forceinline__ void cp_commit() {
    asm volatile("cp.async.commit_group;");
}
__device__ __forceinline__ void cp_wait0() {
    asm volatile("cp.async.wait_group 0;");
}
__device__ __forceinline__ void cp_wait1() {
    asm volatile("cp.async.wait_group 1;");
}
__device__ __forceinline__ void cp_wait2() {
    asm volatile("cp.async.wait_group 2;");
}

// ---------------------------------------------------------------------------
// fp16 tensor-core GEMM v4: ldmatrix + 3-stage cp.async pipeline.
// ---------------------------------------------------------------------------
__global__ __launch_bounds__(256, 2) void gemm_fp16(
    const __half* __restrict__ A, const __half* __restrict__ Bt,
    float* __restrict__ Cm, int M, int N, int K)
{
    __shared__ __align__(16) __half As[3][128 * 32];
    __shared__ __align__(16) __half Bs[3][128 * 32];

    int tid = threadIdx.x;
    int lane = tid & 31;
    int warp = tid >> 5;
    int gid = lane >> 2, tig = lane & 3;
    int warp_m = warp >> 2, warp_n = warp & 3;
    int bm = blockIdx.y, bn = blockIdx.x;

    const __half* Ab = A + (size_t)(bm * 128) * K;
    const __half* Bb = Bt + (size_t)(bn * 128) * K;

    uint32_t asb[3], bsb[3];
    #pragma unroll
    for (int i = 0; i < 3; i++) {
        asb[i] = (uint32_t)__cvta_generic_to_shared(As[i]);
        bsb[i] = (uint32_t)__cvta_generic_to_shared(Bs[i]);
    }

    float acc[4][4][4];
    #pragma unroll
    for (int mt = 0; mt < 4; mt++)
        #pragma unroll
        for (int nt = 0; nt < 4; nt++)
            #pragma unroll
            for (int e = 0; e < 4; e++) acc[mt][nt][e] = 0.f;

    auto issue = [&](int k0, int buf) {
        #pragma unroll
        for (int it = 0; it < 2; it++) {
            int cid = tid + 256 * it;
            int r = cid >> 2;
            int c4 = cid & 3;
            int sc = c4 ^ ((r >> 1) & 3);
            cp16(asb[buf] + (r * 32 + 8 * sc) * 2,
                 Ab + (size_t)r * K + k0 + 8 * c4);
            cp16(bsb[buf] + (r * 32 + 8 * sc) * 2,
                 Bb + (size_t)r * K + k0 + 8 * c4);
        }
        cp_commit();
    };

    int T = K / 32;
    issue(0, 0);
    if (T > 1) issue(32, 1);

    for (int t = 0; t < T; t++) {
        if (t + 2 < T) issue((t + 2) * 32, (t + 2) % 3);
        int rem = T - 1 - t;
        if (rem >= 2) cp_wait2();
        else if (rem == 1) cp_wait1();
        else cp_wait0();
        __syncthreads();

        int buf = t % 3;
        #pragma unroll
        for (int s = 0; s < 2; s++) {
            unsigned afr[4][4];
            unsigned bfr[4][2];
            #pragma unroll
            for (int mt = 0; mt < 4; mt++) {
                int m = warp_m * 64 + mt * 16;
                int row = m + (lane & 15);
                int chunk = 2 * s + (lane >> 4);
                int sc = chunk ^ ((row >> 1) & 3);
                ldsm4(afr[mt][0], afr[mt][1], afr[mt][2], afr[mt][3],
                      asb[buf] + (row * 32 + 8 * sc) * 2);
            }
            #pragma unroll
            for (int nb = 0; nb < 2; nb++) {
                int n0 = warp_n * 32 + nb * 16;
                int row = n0 + (lane & 7) + ((lane >> 4) << 3);
                int chunk = 2 * s + ((lane >> 3) & 1);
                int sc = chunk ^ ((row >> 1) & 3);
                unsigned r0, r1, r2, r3;
                ldsm4(r0, r1, r2, r3, bsb[buf] + (row * 32 + 8 * sc) * 2);
                bfr[2 * nb][0] = r0;     bfr[2 * nb][1] = r1;
                bfr[2 * nb + 1][0] = r2; bfr[2 * nb + 1][1] = r3;
            }
            #pragma unroll
            for (int mt = 0; mt < 4; mt++)
                #pragma unroll
                for (int nt = 0; nt < 4; nt++)
                    mma16(acc[mt][nt], afr[mt], bfr[nt][0], bfr[nt][1]);
        }
        __syncthreads();
    }

    #pragma unroll
    for (int mt = 0; mt < 4; mt++)
        #pragma unroll
        for (int nt = 0; nt < 4; nt++) {
            int row = bm * 128 + warp_m * 64 + mt * 16 + gid;
            int col = bn * 128 + warp_n * 32 + nt * 8 + tig * 2;
            *(float2*)&Cm[(size_t)row * N + col] =
                make_float2(acc[mt][nt][0], acc[mt][nt][1]);
            *(float2*)&Cm[(size_t)(row + 8) * N + col] =
                make_float2(acc[mt][nt][2], acc[mt][nt][3]);
        }
}

// ---------------------------------------------------------------------------
// pre-passes
// ---------------------------------------------------------------------------
__global__ void fp16_round_kernel(const float* __restrict__ in,
                                  __half* __restrict__ out, int n4)
{
    int i = blockIdx.x * blockDim.x + threadIdx.x;
    if (i < n4) {
        float4 v = ((const float4*)in)[i];
        __half2 h0 = __floats2half2_rn(v.x, v.y);
        __half2 h1 = __floats2half2_rn(v.z, v.w);
        ((__half2*)out)[2 * i]     = h0;
        ((__half2*)out)[2 * i + 1] = h1;
    }
}

__global__ __launch_bounds__(256) void transpose_fp16_kernel(
    const float* __restrict__ in, __half* __restrict__ out, int R, int C)
{
    __shared__ float tile[32][33];
    int r0 = blockIdx.y * 32, c0 = blockIdx.x * 32;
    int tx = threadIdx.x & 31, ty = threadIdx.x >> 5;
    #pragma unroll
    for (int i = ty; i < 32; i += 8)
        tile[i][tx] = in[(size_t)(r0 + i) * C + c0 + tx];
    __syncthreads();
    #pragma unroll
    for (int i = ty; i < 32; i += 8)
        out[(size_t)(c0 + i) * R + r0 + tx] = __float2half_rn(tile[tx][i]);
}

// ---------------------------------------------------------------------------
// Split qkv -> q,k [B,H,T,64], V TRANSPOSED [B,H,64,T]; RoPE; q scaled 1/8.
// ---------------------------------------------------------------------------
__global__ void rope_split_kernel()
{
    int idx = blockIdx.x * blockDim.x + threadIdx.x;
    const int total = BB * NH * TT * 32;
    if (idx >= total) return;

    int jj = idx & 31;
    int tmp = idx >> 5;
    int t = tmp & (TT - 1);
    tmp >>= 11;
    int h = tmp & (NH - 1);
    int b = tmp >> 4;
    int bh = b * NH + h;

    const float LOG1E4 = 9.210340371976184f;
    float inv_freq = expf(-(float)jj * (LOG1E4 / 32.0f));
    float ang = (float)t * inv_freq;
    float cs = cosf(ang), sn = sinf(ang);

    size_t src_row = (size_t)(b * TT + t) * C3;
    int col = h * HD + jj;

    float q1 = g_qkv[src_row + col];
    float q2 = g_qkv[src_row + col + 32];
    float k1 = g_qkv[src_row + CC + col];
    float k2 = g_qkv[src_row + CC + col + 32];
    float v1 = g_qkv[src_row + 2 * CC + col];
    float v2 = g_qkv[src_row + 2 * CC + col + 32];

    size_t dst = ((size_t)bh * TT + t) * HD + jj;
    g_qh[dst]      = __float2half_rn((q1 * cs - q2 * sn) * 0.125f);
    g_qh[dst + 32] = __float2half_rn((q2 * cs + q1 * sn) * 0.125f);
    g_kh[dst]      = __float2half_rn(k1 * cs - k2 * sn);
    g_kh[dst + 32] = __float2half_rn(k2 * cs + k1 * sn);

    size_t vdst = ((size_t)bh * HD + jj) * TT + t;
    g_vt[vdst]           = __float2half_rn(v1);
    g_vt[vdst + 32 * TT] = __float2half_rn(v2);
}

// ---------------------------------------------------------------------------
// Flash attention (causal), fp16 mma, v4: kv-tile 128, two 64-kv softmax
// sub-phases (identical update order -> bit-identical), cp.async double
// buffer, fully-masked warp-strips skipped.
// Smem (uint32): sQ[128*36] | sK[2][128*36] | sV[2][64*68] = 88 KB dynamic.
// ---------------------------------------------------------------------------
#define AT_QW (128 * 36)
#define AT_KW (128 * 36)
#define AT_VW (64 * 68)
#define ATTN_SMEM_WORDS (AT_QW + 2 * AT_KW + 2 * AT_VW)

__global__ __launch_bounds__(256, 2) void attn_mma_kernel()
{
    extern __shared__ unsigned smw[];
    unsigned* sQ = smw;
    unsigned* sK[2] = { smw + AT_QW, smw + AT_QW + AT_KW };
    unsigned* sV[2] = { smw + AT_QW + 2 * AT_KW, smw + AT_QW + 2 * AT_KW + AT_VW };

    int tid = threadIdx.x;
    int lane = tid & 31;
    int warp = tid >> 5;
    int gid = lane >> 2, tig = lane & 3;
    int qb = blockIdx.x;
    int bh = blockIdx.y;

    const __half* Qg = g_qh + ((size_t)bh * TT + qb * 128) * HD;
    const __half* Kg = g_kh + (size_t)bh * TT * HD;
    const __half* VTg = g_vt + (size_t)bh * HD * TT;

    uint32_t qsb = (uint32_t)__cvta_generic_to_shared(sQ);
    uint32_t ksb[2], vsb[2];
    ksb[0] = (uint32_t)__cvta_generic_to_shared(sK[0]);
    ksb[1] = (uint32_t)__cvta_generic_to_shared(sK[1]);
    vsb[0] = (uint32_t)__cvta_generic_to_shared(sV[0]);
    vsb[1] = (uint32_t)__cvta_generic_to_shared(sV[1]);

    auto issue_kv = [&](int kb, int buf) {
        #pragma unroll
        for (int i = 0; i < 4; i++) {
            int cid = tid + 256 * i;
            int r = cid >> 3;          // 0..127
            int j = cid & 7;
            cp16(ksb[buf] + (r * 36 + 4 * j) * 4,
                 Kg + (size_t)(kb * 128 + r) * 64 + 8 * j);
        }
        #pragma unroll
        for (int i = 0; i < 4; i++) {
            int cid = tid + 256 * i;
            int d = cid >> 4;          // 0..63
            int j = cid & 15;
            cp16(vsb[buf] + (d * 68 + 4 * j) * 4,
                 VTg + (size_t)d * TT + kb * 128 + 8 * j);
        }
        cp_commit();
    };

    #pragma unroll
    for (int i = 0; i < 4; i++) {
        int cid = tid + 256 * i;
        int r = cid >> 3;
        int j = cid & 7;
        cp16(qsb + (r * 36 + 4 * j) * 4, Qg + (size_t)r * 64 + 8 * j);
    }
    issue_kv(0, 0);

    float oacc[8][4];
    #pragma unroll
    for (int nt = 0; nt < 8; nt++)
        #pragma unroll
        for (int e = 0; e < 4; e++) oacc[nt][e] = 0.f;
    float rm0 = -1e30f, rm1 = -1e30f, rl0 = 0.f, rl1 = 0.f;

    int wrow = qb * 128 + warp * 16;
    int row1 = wrow + gid;
    int row2 = row1 + 8;

    unsigned qa[4][4];

    int kb_max = qb;
    for (int kb = 0; kb <= kb_max; kb++) {
        bool has_next = (kb < kb_max);
        if (has_next) issue_kv(kb + 1, (kb + 1) & 1);
        if (has_next) cp_wait1(); else cp_wait0();
        __syncthreads();

        int buf = kb & 1;
        const unsigned* K_ = sK[buf];
        const unsigned* V_ = sV[buf];

        if (kb == 0) {
            int ml = warp * 16 + gid;
            #pragma unroll
            for (int s = 0; s < 4; s++) {
                qa[s][0] = sQ[ml * 36 + 8 * s + tig];
                qa[s][1] = sQ[(ml + 8) * 36 + 8 * s + tig];
                qa[s][2] = sQ[ml * 36 + 8 * s + tig + 4];
                qa[s][3] = sQ[(ml + 8) * 36 + 8 * s + tig + 4];
            }
        }

        #pragma unroll
        for (int half = 0; half < 2; half++) {
            int base = kb * 128 + half * 64;
            if (base > wrow + 15) continue;

            float sacc[8][4];
            #pragma unroll
            for (int nt = 0; nt < 8; nt++)
                #pragma unroll
                for (int e = 0; e < 4; e++) sacc[nt][e] = 0.f;

            #pragma unroll
            for (int s = 0; s < 4; s++) {
                #pragma unroll
                for (int nt = 0; nt < 8; nt++) {
                    int n = half * 64 + nt * 8 + gid;
                    unsigned b0 = K_[n * 36 + 8 * s + tig];
                    unsigned b1 = K_[n * 36 + 8 * s + tig + 4];
                    mma16(sacc[nt], qa[s], b0, b1);
                }
            }

            if (base + 63 > wrow) {
                #pragma unroll
                for (int nt = 0; nt < 8; nt++) {
                    int colb = base + nt * 8 + tig * 2;
                    if (colb + 0 > row1) sacc[nt][0] = -1e30f;
                    if (colb + 1 > row1) sacc[nt][1] = -1e30f;
                    if (colb + 0 > row2) sacc[nt][2] = -1e30f;
                    if (colb + 1 > row2) sacc[nt][3] = -1e30f;
                }
            }

            float mx0 = -1e30f, mx1 = -1e30f;
            #pragma unroll
            for (int nt = 0; nt < 8; nt++) {
                mx0 = fmaxf(mx0, fmaxf(sacc[nt][0], sacc[nt][1]));
                mx1 = fmaxf(mx1, fmaxf(sacc[nt][2], sacc[nt][3]));
            }
            mx0 = fmaxf(mx0, __shfl_xor_sync(0xffffffffu, mx0, 1));
            mx0 = fmaxf(mx0, __shfl_xor_sync(0xffffffffu, mx0, 2));
            mx1 = fmaxf(mx1, __shfl_xor_sync(0xffffffffu, mx1, 1));
            mx1 = fmaxf(mx1, __shfl_xor_sync(0xffffffffu, mx1, 2));

            float mn0 = fmaxf(rm0, mx0);
            float mn1 = fmaxf(rm1, mx1);
            float corr0 = __expf(rm0 - mn0);
            float corr1 = __expf(rm1 - mn1);
            rm0 = mn0; rm1 = mn1;

            float sum0 = 0.f, sum1 = 0.f;
            #pragma unroll
            for (int nt = 0; nt < 8; nt++) {
                sacc[nt][0] = __expf(sacc[nt][0] - mn0);
                sacc[nt][1] = __expf(sacc[nt][1] - mn0);
                sacc[nt][2] = __expf(sacc[nt][2] - mn1);
                sacc[nt][3] = __expf(sacc[nt][3] - mn1);
                sum0 += sacc[nt][0] + sacc[nt][1];
                sum1 += sacc[nt][2] + sacc[nt][3];
            }
            sum0 += __shfl_xor_sync(0xffffffffu, sum0, 1);
            sum0 += __shfl_xor_sync(0xffffffffu, sum0, 2);
            sum1 += __shfl_xor_sync(0xffffffffu, sum1, 1);
            sum1 += __shfl_xor_sync(0xffffffffu, sum1, 2);
            rl0 = rl0 * corr0 + sum0;
            rl1 = rl1 * corr1 + sum1;

            #pragma unroll
            for (int nt = 0; nt < 8; nt++) {
                oacc[nt][0] *= corr0; oacc[nt][1] *= corr0;
                oacc[nt][2] *= corr1; oacc[nt][3] *= corr1;
            }

            #pragma unroll
            for (int s = 0; s < 4; s++) {
                unsigned pa[4];
                pa[0] = h2u(__floats2half2_rn(sacc[2 * s][0],     sacc[2 * s][1]));
                pa[1] = h2u(__floats2half2_rn(sacc[2 * s][2],     sacc[2 * s][3]));
                pa[2] = h2u(__floats2half2_rn(sacc[2 * s + 1][0], sacc[2 * s + 1][1]));
                pa[3] = h2u(__floats2half2_rn(sacc[2 * s + 1][2], sacc[2 * s + 1][3]));
                #pragma unroll
                for (int dt = 0; dt < 8; dt++) {
                    int n = dt * 8 + gid;
                    unsigned b0 = V_[n * 68 + 32 * half + 8 * s + tig];
                    unsigned b1 = V_[n * 68 + 32 * half + 8 * s + tig + 4];
                    mma16(oacc[dt], pa, b0, b1);
                }
            }
        }
        __syncthreads();
    }

    int b = bh >> 4;
    int h = bh & (NH - 1);
    float il0 = 1.f / rl0;
    float il1 = 1.f / rl1;
    #pragma unroll
    for (int nt = 0; nt < 8; nt++) {
        int d = nt * 8 + tig * 2;
        *(__half2*)&g_attnh[((size_t)(b * TT + row1)) * CC + h * 64 + d] =
            __floats2half2_rn(oacc[nt][0] * il0, oacc[nt][1] * il0);
        *(__half2*)&g_attnh[((size_t)(b * TT + row2)) * CC + h * 64 + d] =
            __floats2half2_rn(oacc[nt][2] * il1, oacc[nt][3] * il1);
    }
}

// ---------------------------------------------------------------------------
extern "C" void kernel_launch(void* const* d_in, const int* in_sizes, int n_in,
                              void* d_out, int out_size)
{
    const float* x     = (const float*)d_in[0];
    const float* w_qkv = (const float*)d_in[1];
    const float* w_out = (const float*)d_in[2];
    float* out = (float*)d_out;

    float *qkv_p;
    __half *xh_p, *w1h_p, *w2h_p, *attnh_p;
    cudaGetSymbolAddress((void**)&qkv_p,   g_qkv);
    cudaGetSymbolAddress((void**)&xh_p,    g_xh);
    cudaGetSymbolAddress((void**)&w1h_p,   g_w1h);
    cudaGetSymbolAddress((void**)&w2h_p,   g_w2h);
    cudaGetSymbolAddress((void**)&attnh_p, g_attnh);

    // 0) operand prep
    {
        int n4 = BT * CC / 4;
        fp16_round_kernel<<<(n4 + 255) / 256, 256>>>(x, xh_p, n4);
        dim3 g1(C3 / 32, CC / 32);
        transpose_fp16_kernel<<<g1, 256>>>(w_qkv, w1h_p, CC, C3);
        dim3 g2(CC / 32, CC / 32);
        transpose_fp16_kernel<<<g2, 256>>>(w_out, w2h_p, CC, CC);
    }

    // 1) QKV projection
    {
        dim3 grid(C3 / 128, BT / 128);
        gemm_fp16<<<grid, 256>>>(xh_p, w1h_p, qkv_p, BT, C3, CC);
    }

    // 2) split + RoPE
    {
        int total = BB * NH * TT * 32;
        rope_split_kernel<<<(total + 255) / 256, 256>>>();
    }

    // 3) flash attention
    {
        int smem_bytes = ATTN_SMEM_WORDS * sizeof(unsigned);
        cudaFuncSetAttribute(attn_mma_kernel,
                             cudaFuncAttributeMaxDynamicSharedMemorySize,
                             smem_bytes);
        dim3 grid(TT / 128, BB * NH);
        attn_mma_kernel<<<grid, 256, smem_bytes>>>();
    }

    // 4) output projection
    {
        dim3 grid(CC / 128, BT / 128);
        gemm_fp16<<<grid, 256>>>(attnh_p, w2h_p, out, BT, CC, CC);
    }
}

// round 17
// speedup vs baseline: 2.3046x; 1.0336x over previous
#include <cuda_runtime.h>
#include <cuda_fp16.h>
#include <math.h>
#include <stdint.h>

#define BB 4
#define TT 2048
#define CC 1024
#define NH 16
#define HD 64
#define BT (BB*TT)      // 8192
#define C3 (3*CC)       // 3072

// Scratch (device globals; no allocation allowed)
__device__ float  g_qkv[BT * C3];    // [BT, 3C] fp32
__device__ __half g_qh[BT * CC];     // [B,H,T,64] fp16, pre-scaled 1/8
__device__ __half g_kh[BT * CC];     // [B,H,T,64] fp16
__device__ __half g_vt[BT * CC];     // [B,H,64,T] fp16  (V transposed)
__device__ __half g_attnh[BT * CC];  // [B,T,C] fp16
__device__ __half g_xh[BT * CC];     // fp16 x
__device__ __half g_w1h[C3 * CC];    // w_qkv transposed -> [3C, C] fp16
__device__ __half g_w2h[CC * CC];    // w_out transposed -> [C, C] fp16

// ---------------------------------------------------------------------------
// helpers
// ---------------------------------------------------------------------------
__device__ __forceinline__ void mma16(float* c, const unsigned* a,
                                      unsigned b0, unsigned b1) {
    asm("mma.sync.aligned.m16n8k16.row.col.f32.f16.f16.f32 "
        "{%0,%1,%2,%3}, {%4,%5,%6,%7}, {%8,%9}, {%0,%1,%2,%3};"
        : "+f"(c[0]), "+f"(c[1]), "+f"(c[2]), "+f"(c[3])
        : "r"(a[0]), "r"(a[1]), "r"(a[2]), "r"(a[3]), "r"(b0), "r"(b1));
}

__device__ __forceinline__ unsigned h2u(__half2 h) {
    return *reinterpret_cast<unsigned*>(&h);
}

__device__ __forceinline__ void ldsm4(unsigned& r0, unsigned& r1,
                                      unsigned& r2, unsigned& r3,
                                      uint32_t addr) {
    asm volatile("ldmatrix.sync.aligned.m8n8.x4.shared.b16 {%0,%1,%2,%3}, [%4];"
                 : "=r"(r0), "=r"(r1), "=r"(r2), "=r"(r3) : "r"(addr));
}

__device__ __forceinline__ void cp16(uint32_t dst, const void* src) {
    asm volatile("cp.async.cg.shared.global [%0], [%1], 16;" :: "r"(dst), "l"(src));
}
__device__ __forceinline__ void cp_commit() {
    asm volatile("cp.async.commit_group;");
}
__device__ __forceinline__ void cp_wait0() {
    asm volatile("cp.async.wait_group 0;");
}
__device__ __forceinline__ void cp_wait1() {
    asm volatile("cp.async.wait_group 1;");
}

// ---------------------------------------------------------------------------
// fp16 tensor-core GEMM (R14, proven fastest): ldmatrix + 2-stage cp.async.
// C[M,N] = A[M,K] @ Bt[N,K]^T, fp32 accum. CTA tile 128x128, k-tile 32,
// 8 warps 2(m) x 4(n). Smem: k-major rows of 32 halves, 16B-chunk swizzle
// c4 ^= (r>>1)&3.  Requires M%128==0, N%128==0, K%32==0.
// ---------------------------------------------------------------------------
__global__ __launch_bounds__(256) void gemm_fp16(
    const __half* __restrict__ A, const __half* __restrict__ Bt,
    float* __restrict__ Cm, int M, int N, int K)
{
    __shared__ __align__(16) __half As[2][128 * 32];
    __shared__ __align__(16) __half Bs[2][128 * 32];

    int tid = threadIdx.x;
    int lane = tid & 31;
    int warp = tid >> 5;
    int gid = lane >> 2, tig = lane & 3;
    int warp_m = warp >> 2, warp_n = warp & 3;
    int bm = blockIdx.y, bn = blockIdx.x;

    const __half* Ab = A + (size_t)(bm * 128) * K;
    const __half* Bb = Bt + (size_t)(bn * 128) * K;

    uint32_t asb[2], bsb[2];
    asb[0] = (uint32_t)__cvta_generic_to_shared(As[0]);
    asb[1] = (uint32_t)__cvta_generic_to_shared(As[1]);
    bsb[0] = (uint32_t)__cvta_generic_to_shared(Bs[0]);
    bsb[1] = (uint32_t)__cvta_generic_to_shared(Bs[1]);

    float acc[4][4][4];
    #pragma unroll
    for (int mt = 0; mt < 4; mt++)
        #pragma unroll
        for (int nt = 0; nt < 4; nt++)
            #pragma unroll
            for (int e = 0; e < 4; e++) acc[mt][nt][e] = 0.f;

    auto issue = [&](int k0, int buf) {
        #pragma unroll
        for (int it = 0; it < 2; it++) {
            int cid = tid + 256 * it;
            int r = cid >> 2;
            int c4 = cid & 3;
            int sc = c4 ^ ((r >> 1) & 3);
            cp16(asb[buf] + (r * 32 + 8 * sc) * 2,
                 Ab + (size_t)r * K + k0 + 8 * c4);
            cp16(bsb[buf] + (r * 32 + 8 * sc) * 2,
                 Bb + (size_t)r * K + k0 + 8 * c4);
        }
        cp_commit();
    };

    int T = K / 32;
    issue(0, 0);

    for (int t = 0; t < T; t++) {
        bool has_next = (t + 1 < T);
        if (has_next) issue((t + 1) * 32, (t + 1) & 1);
        if (has_next) cp_wait1(); else cp_wait0();
        __syncthreads();

        int buf = t & 1;
        #pragma unroll
        for (int s = 0; s < 2; s++) {
            unsigned afr[4][4];
            unsigned bfr[4][2];
            #pragma unroll
            for (int mt = 0; mt < 4; mt++) {
                int m = warp_m * 64 + mt * 16;
                int row = m + (lane & 15);
                int chunk = 2 * s + (lane >> 4);
                int sc = chunk ^ ((row >> 1) & 3);
                ldsm4(afr[mt][0], afr[mt][1], afr[mt][2], afr[mt][3],
                      asb[buf] + (row * 32 + 8 * sc) * 2);
            }
            #pragma unroll
            for (int nb = 0; nb < 2; nb++) {
                int n0 = warp_n * 32 + nb * 16;
                int row = n0 + (lane & 7) + ((lane >> 4) << 3);
                int chunk = 2 * s + ((lane >> 3) & 1);
                int sc = chunk ^ ((row >> 1) & 3);
                unsigned r0, r1, r2, r3;
                ldsm4(r0, r1, r2, r3, bsb[buf] + (row * 32 + 8 * sc) * 2);
                bfr[2 * nb][0] = r0;     bfr[2 * nb][1] = r1;
                bfr[2 * nb + 1][0] = r2; bfr[2 * nb + 1][1] = r3;
            }
            #pragma unroll
            for (int mt = 0; mt < 4; mt++)
                #pragma unroll
                for (int nt = 0; nt < 4; nt++)
                    mma16(acc[mt][nt], afr[mt], bfr[nt][0], bfr[nt][1]);
        }
        __syncthreads();
    }

    #pragma unroll
    for (int mt = 0; mt < 4; mt++)
        #pragma unroll
        for (int nt = 0; nt < 4; nt++) {
            int row = bm * 128 + warp_m * 64 + mt * 16 + gid;
            int col = bn * 128 + warp_n * 32 + nt * 8 + tig * 2;
            *(float2*)&Cm[(size_t)row * N + col] =
                make_float2(acc[mt][nt][0], acc[mt][nt][1]);
            *(float2*)&Cm[(size_t)(row + 8) * N + col] =
                make_float2(acc[mt][nt][2], acc[mt][nt][3]);
        }
}

// ---------------------------------------------------------------------------
// pre-passes
// ---------------------------------------------------------------------------
__global__ void fp16_round_kernel(const float* __restrict__ in,
                                  __half* __restrict__ out, int n4)
{
    int i = blockIdx.x * blockDim.x + threadIdx.x;
    if (i < n4) {
        float4 v = ((const float4*)in)[i];
        __half2 h0 = __floats2half2_rn(v.x, v.y);
        __half2 h1 = __floats2half2_rn(v.z, v.w);
        ((__half2*)out)[2 * i]     = h0;
        ((__half2*)out)[2 * i + 1] = h1;
    }
}

__global__ __launch_bounds__(256) void transpose_fp16_kernel(
    const float* __restrict__ in, __half* __restrict__ out, int R, int C)
{
    __shared__ float tile[32][33];
    int r0 = blockIdx.y * 32, c0 = blockIdx.x * 32;
    int tx = threadIdx.x & 31, ty = threadIdx.x >> 5;
    #pragma unroll
    for (int i = ty; i < 32; i += 8)
        tile[i][tx] = in[(size_t)(r0 + i) * C + c0 + tx];
    __syncthreads();
    #pragma unroll
    for (int i = ty; i < 32; i += 8)
        out[(size_t)(c0 + i) * R + r0 + tx] = __float2half_rn(tile[tx][i]);
}

// ---------------------------------------------------------------------------
// Split qkv -> q,k [B,H,T,64], V TRANSPOSED [B,H,64,T]; RoPE; q scaled 1/8.
// ---------------------------------------------------------------------------
__global__ void rope_split_kernel()
{
    int idx = blockIdx.x * blockDim.x + threadIdx.x;
    const int total = BB * NH * TT * 32;
    if (idx >= total) return;

    int jj = idx & 31;
    int tmp = idx >> 5;
    int t = tmp & (TT - 1);
    tmp >>= 11;
    int h = tmp & (NH - 1);
    int b = tmp >> 4;
    int bh = b * NH + h;

    const float LOG1E4 = 9.210340371976184f;
    float inv_freq = expf(-(float)jj * (LOG1E4 / 32.0f));
    float ang = (float)t * inv_freq;
    float cs = cosf(ang), sn = sinf(ang);

    size_t src_row = (size_t)(b * TT + t) * C3;
    int col = h * HD + jj;

    float q1 = g_qkv[src_row + col];
    float q2 = g_qkv[src_row + col + 32];
    float k1 = g_qkv[src_row + CC + col];
    float k2 = g_qkv[src_row + CC + col + 32];
    float v1 = g_qkv[src_row + 2 * CC + col];
    float v2 = g_qkv[src_row + 2 * CC + col + 32];

    size_t dst = ((size_t)bh * TT + t) * HD + jj;
    g_qh[dst]      = __float2half_rn((q1 * cs - q2 * sn) * 0.125f);
    g_qh[dst + 32] = __float2half_rn((q2 * cs + q1 * sn) * 0.125f);
    g_kh[dst]      = __float2half_rn(k1 * cs - k2 * sn);
    g_kh[dst + 32] = __float2half_rn(k2 * cs + k1 * sn);

    size_t vdst = ((size_t)bh * HD + jj) * TT + t;
    g_vt[vdst]           = __float2half_rn(v1);
    g_vt[vdst + 32 * TT] = __float2half_rn(v2);
}

// ---------------------------------------------------------------------------
// Flash attention (causal), fp16 mma, v4 (R16, proven): kv-tile 128, two
// 64-kv softmax sub-phases, cp.async double buffer, fully-masked warp-strips
// skipped.
// Smem (uint32): sQ[128*36] | sK[2][128*36] | sV[2][64*68] = 88 KB dynamic.
// ---------------------------------------------------------------------------
#define AT_QW (128 * 36)
#define AT_KW (128 * 36)
#define AT_VW (64 * 68)
#define ATTN_SMEM_WORDS (AT_QW + 2 * AT_KW + 2 * AT_VW)

__global__ __launch_bounds__(256, 2) void attn_mma_kernel()
{
    extern __shared__ unsigned smw[];
    unsigned* sQ = smw;
    unsigned* sK[2] = { smw + AT_QW, smw + AT_QW + AT_KW };
    unsigned* sV[2] = { smw + AT_QW + 2 * AT_KW, smw + AT_QW + 2 * AT_KW + AT_VW };

    int tid = threadIdx.x;
    int lane = tid & 31;
    int warp = tid >> 5;
    int gid = lane >> 2, tig = lane & 3;
    int qb = blockIdx.x;
    int bh = blockIdx.y;

    const __half* Qg = g_qh + ((size_t)bh * TT + qb * 128) * HD;
    const __half* Kg = g_kh + (size_t)bh * TT * HD;
    const __half* VTg = g_vt + (size_t)bh * HD * TT;

    uint32_t qsb = (uint32_t)__cvta_generic_to_shared(sQ);
    uint32_t ksb[2], vsb[2];
    ksb[0] = (uint32_t)__cvta_generic_to_shared(sK[0]);
    ksb[1] = (uint32_t)__cvta_generic_to_shared(sK[1]);
    vsb[0] = (uint32_t)__cvta_generic_to_shared(sV[0]);
    vsb[1] = (uint32_t)__cvta_generic_to_shared(sV[1]);

    auto issue_kv = [&](int kb, int buf) {
        #pragma unroll
        for (int i = 0; i < 4; i++) {
            int cid = tid + 256 * i;
            int r = cid >> 3;          // 0..127
            int j = cid & 7;
            cp16(ksb[buf] + (r * 36 + 4 * j) * 4,
                 Kg + (size_t)(kb * 128 + r) * 64 + 8 * j);
        }
        #pragma unroll
        for (int i = 0; i < 4; i++) {
            int cid = tid + 256 * i;
            int d = cid >> 4;          // 0..63
            int j = cid & 15;
            cp16(vsb[buf] + (d * 68 + 4 * j) * 4,
                 VTg + (size_t)d * TT + kb * 128 + 8 * j);
        }
        cp_commit();
    };

    #pragma unroll
    for (int i = 0; i < 4; i++) {
        int cid = tid + 256 * i;
        int r = cid >> 3;
        int j = cid & 7;
        cp16(qsb + (r * 36 + 4 * j) * 4, Qg + (size_t)r * 64 + 8 * j);
    }
    issue_kv(0, 0);

    float oacc[8][4];
    #pragma unroll
    for (int nt = 0; nt < 8; nt++)
        #pragma unroll
        for (int e = 0; e < 4; e++) oacc[nt][e] = 0.f;
    float rm0 = -1e30f, rm1 = -1e30f, rl0 = 0.f, rl1 = 0.f;

    int wrow = qb * 128 + warp * 16;
    int row1 = wrow + gid;
    int row2 = row1 + 8;

    unsigned qa[4][4];

    int kb_max = qb;
    for (int kb = 0; kb <= kb_max; kb++) {
        bool has_next = (kb < kb_max);
        if (has_next) issue_kv(kb + 1, (kb + 1) & 1);
        if (has_next) cp_wait1(); else cp_wait0();
        __syncthreads();

        int buf = kb & 1;
        const unsigned* K_ = sK[buf];
        const unsigned* V_ = sV[buf];

        if (kb == 0) {
            int ml = warp * 16 + gid;
            #pragma unroll
            for (int s = 0; s < 4; s++) {
                qa[s][0] = sQ[ml * 36 + 8 * s + tig];
                qa[s][1] = sQ[(ml + 8) * 36 + 8 * s + tig];
                qa[s][2] = sQ[ml * 36 + 8 * s + tig + 4];
                qa[s][3] = sQ[(ml + 8) * 36 + 8 * s + tig + 4];
            }
        }

        #pragma unroll
        for (int half = 0; half < 2; half++) {
            int base = kb * 128 + half * 64;
            if (base > wrow + 15) continue;

            float sacc[8][4];
            #pragma unroll
            for (int nt = 0; nt < 8; nt++)
                #pragma unroll
                for (int e = 0; e < 4; e++) sacc[nt][e] = 0.f;

            #pragma unroll
            for (int s = 0; s < 4; s++) {
                #pragma unroll
                for (int nt = 0; nt < 8; nt++) {
                    int n = half * 64 + nt * 8 + gid;
                    unsigned b0 = K_[n * 36 + 8 * s + tig];
                    unsigned b1 = K_[n * 36 + 8 * s + tig + 4];
                    mma16(sacc[nt], qa[s], b0, b1);
                }
            }

            if (base + 63 > wrow) {
                #pragma unroll
                for (int nt = 0; nt < 8; nt++) {
                    int colb = base + nt * 8 + tig * 2;
                    if (colb + 0 > row1) sacc[nt][0] = -1e30f;
                    if (colb + 1 > row1) sacc[nt][1] = -1e30f;
                    if (colb + 0 > row2) sacc[nt][2] = -1e30f;
                    if (colb + 1 > row2) sacc[nt][3] = -1e30f;
                }
            }

            float mx0 = -1e30f, mx1 = -1e30f;
            #pragma unroll
            for (int nt = 0; nt < 8; nt++) {
                mx0 = fmaxf(mx0, fmaxf(sacc[nt][0], sacc[nt][1]));
                mx1 = fmaxf(mx1, fmaxf(sacc[nt][2], sacc[nt][3]));
            }
            mx0 = fmaxf(mx0, __shfl_xor_sync(0xffffffffu, mx0, 1));
            mx0 = fmaxf(mx0, __shfl_xor_sync(0xffffffffu, mx0, 2));
            mx1 = fmaxf(mx1, __shfl_xor_sync(0xffffffffu, mx1, 1));
            mx1 = fmaxf(mx1, __shfl_xor_sync(0xffffffffu, mx1, 2));

            float mn0 = fmaxf(rm0, mx0);
            float mn1 = fmaxf(rm1, mx1);
            float corr0 = __expf(rm0 - mn0);
            float corr1 = __expf(rm1 - mn1);
            rm0 = mn0; rm1 = mn1;

            float sum0 = 0.f, sum1 = 0.f;
            #pragma unroll
            for (int nt = 0; nt < 8; nt++) {
                sacc[nt][0] = __expf(sacc[nt][0] - mn0);
                sacc[nt][1] = __expf(sacc[nt][1] - mn0);
                sacc[nt][2] = __expf(sacc[nt][2] - mn1);
                sacc[nt][3] = __expf(sacc[nt][3] - mn1);
                sum0 += sacc[nt][0] + sacc[nt][1];
                sum1 += sacc[nt][2] + sacc[nt][3];
            }
            sum0 += __shfl_xor_sync(0xffffffffu, sum0, 1);
            sum0 += __shfl_xor_sync(0xffffffffu, sum0, 2);
            sum1 += __shfl_xor_sync(0xffffffffu, sum1, 1);
            sum1 += __shfl_xor_sync(0xffffffffu, sum1, 2);
            rl0 = rl0 * corr0 + sum0;
            rl1 = rl1 * corr1 + sum1;

            #pragma unroll
            for (int nt = 0; nt < 8; nt++) {
                oacc[nt][0] *= corr0; oacc[nt][1] *= corr0;
                oacc[nt][2] *= corr1; oacc[nt][3] *= corr1;
            }

            #pragma unroll
            for (int s = 0; s < 4; s++) {
                unsigned pa[4];
                pa[0] = h2u(__floats2half2_rn(sacc[2 * s][0],     sacc[2 * s][1]));
                pa[1] = h2u(__floats2half2_rn(sacc[2 * s][2],     sacc[2 * s][3]));
                pa[2] = h2u(__floats2half2_rn(sacc[2 * s + 1][0], sacc[2 * s + 1][1]));
                pa[3] = h2u(__floats2half2_rn(sacc[2 * s + 1][2], sacc[2 * s + 1][3]));
                #pragma unroll
                for (int dt = 0; dt < 8; dt++) {
                    int n = dt * 8 + gid;
                    unsigned b0 = V_[n * 68 + 32 * half + 8 * s + tig];
                    unsigned b1 = V_[n * 68 + 32 * half + 8 * s + tig + 4];
                    mma16(oacc[dt], pa, b0, b1);
                }
            }
        }
        __syncthreads();
    }

    int b = bh >> 4;
    int h = bh & (NH - 1);
    float il0 = 1.f / rl0;
    float il1 = 1.f / rl1;
    #pragma unroll
    for (int nt = 0; nt < 8; nt++) {
        int d = nt * 8 + tig * 2;
        *(__half2*)&g_attnh[((size_t)(b * TT + row1)) * CC + h * 64 + d] =
            __floats2half2_rn(oacc[nt][0] * il0, oacc[nt][1] * il0);
        *(__half2*)&g_attnh[((size_t)(b * TT + row2)) * CC + h * 64 + d] =
            __floats2half2_rn(oacc[nt][2] * il1, oacc[nt][3] * il1);
    }
}

// ---------------------------------------------------------------------------
extern "C" void kernel_launch(void* const* d_in, const int* in_sizes, int n_in,
                              void* d_out, int out_size)
{
    const float* x     = (const float*)d_in[0];
    const float* w_qkv = (const float*)d_in[1];
    const float* w_out = (const float*)d_in[2];
    float* out = (float*)d_out;

    float *qkv_p;
    __half *xh_p, *w1h_p, *w2h_p, *attnh_p;
    cudaGetSymbolAddress((void**)&qkv_p,   g_qkv);
    cudaGetSymbolAddress((void**)&xh_p,    g_xh);
    cudaGetSymbolAddress((void**)&w1h_p,   g_w1h);
    cudaGetSymbolAddress((void**)&w2h_p,   g_w2h);
    cudaGetSymbolAddress((void**)&attnh_p, g_attnh);

    // 0) operand prep
    {
        int n4 = BT * CC / 4;
        fp16_round_kernel<<<(n4 + 255) / 256, 256>>>(x, xh_p, n4);
        dim3 g1(C3 / 32, CC / 32);
        transpose_fp16_kernel<<<g1, 256>>>(w_qkv, w1h_p, CC, C3);
        dim3 g2(CC / 32, CC / 32);
        transpose_fp16_kernel<<<g2, 256>>>(w_out, w2h_p, CC, CC);
    }

    // 1) QKV projection
    {
        dim3 grid(C3 / 128, BT / 128);
        gemm_fp16<<<grid, 256>>>(xh_p, w1h_p, qkv_p, BT, C3, CC);
    }

    // 2) split + RoPE
    {
        int total = BB * NH * TT * 32;
        rope_split_kernel<<<(total + 255) / 256, 256>>>();
    }

    // 3) flash attention
    {
        int smem_bytes = ATTN_SMEM_WORDS * sizeof(unsigned);
        cudaFuncSetAttribute(attn_mma_kernel,
                             cudaFuncAttributeMaxDynamicSharedMemorySize,
                             smem_bytes);
        dim3 grid(TT / 128, BB * NH);
        attn_mma_kernel<<<grid, 256, smem_bytes>>>();
    }

    // 4) output projection
    {
        dim3 grid(CC / 128, BT / 128);
        gemm_fp16<<<grid, 256>>>(attnh_p, w2h_p, out, BT, CC, CC);
    }
}